// round 12
// baseline (speedup 1.0000x reference)
#include <cuda_runtime.h>
#include <cuda_bf16.h>
#include <cuda_fp16.h>
#include <math.h>
#include <stdint.h>

#define NSYM   100000
#define PADID  100000
#define B      4096
#define FEW    5
#define MAXK   50
#define KNEI   10
#define EPS    1e-8f
#define LNEPS  1e-5f

// ---------------------------------------------------------------------------
// Scratch (device globals -- no allocations allowed)
// ---------------------------------------------------------------------------
__device__ __align__(128) float g_P[(NSYM + 1) * 256];
__device__ __align__(128) float g_qvec[B * 256];
__device__ __align__(128) float g_svec[FEW * 256];
__device__ __align__(128) float g_sh[FEW * 256];     // LN'd support rows
__device__ __align__(128) float g_sg[256];
__device__ __align__(128) float g_sgn[1];
__device__ __align__(128) float g_H1[B * 512];
__device__ __align__(128) float g_tmp[B * 256];
__device__ __align__(128) float g_X[B * 256];
__device__ __align__(128) float g_whhr[1024];
__device__ __align__(128) __half g_Gq[B * 1024];
__device__ __align__(128) float g_c[B * 256];
__device__ __align__(128) float g_h[B * 256];
__device__ __align__(128) float g_h2[B * 256];

__device__ __forceinline__ float fast_tanh(float x) {
    float y;
    asm("tanh.approx.f32 %0, %1;" : "=f"(y) : "f"(x));
    return y;
}
__device__ __forceinline__ float fast_sig(float x) {
    return 0.5f * fast_tanh(0.5f * x) + 0.5f;
}

__device__ __forceinline__ uint32_t f2tf32(float x) {
    uint32_t r;
    asm("cvt.rna.tf32.f32 %0, %1;" : "=r"(r) : "f"(x));
    return r;
}

#define MMA_TF32(d, a, b)                                                     \
    asm volatile("mma.sync.aligned.m16n8k8.row.col.f32.tf32.tf32.f32 "        \
                 "{%0,%1,%2,%3}, {%4,%5,%6,%7}, {%8,%9}, {%0,%1,%2,%3};"      \
                 : "+f"(d[0]), "+f"(d[1]), "+f"(d[2]), "+f"(d[3])             \
                 : "r"(a[0]), "r"(a[1]), "r"(a[2]), "r"(a[3]),                \
                   "r"(b[0]), "r"(b[1]))

#define MMA_BF16(d, a, b)                                                     \
    asm volatile("mma.sync.aligned.m16n8k16.row.col.f32.bf16.bf16.f32 "       \
                 "{%0,%1,%2,%3}, {%4,%5,%6,%7}, {%8,%9}, {%0,%1,%2,%3};"      \
                 : "+f"(d[0]), "+f"(d[1]), "+f"(d[2]), "+f"(d[3])             \
                 : "r"(a[0]), "r"(a[1]), "r"(a[2]), "r"(a[3]),                \
                   "r"(b[0]), "r"(b[1]))

// LSTM packed-row permutation: packed j -> source row jm
__device__ __forceinline__ int lstm_perm(int j) { return (j & 3) * 512 + (j >> 2); }

// ---------------------------------------------------------------------------
// TF32 tensor-core GEMM with register prefetch (single smem buffer).
// C[M,N] = A[M,K] @ B[N,K]^T ; optional permuted B-row indexing (bpermB).
// EPI=0: generic (+bias +res +relu). EPI=1: LSTM step 1 (bias = bih+bhh via
// perm, fp16 gate store, fused h/c, c0=0). EPI=2: LSTM steps 2-4 (bias=whhr
// packed, fp16 Gq residual, fused h/c).
// ---------------------------------------------------------------------------
#define SMS 36
template <int EPI>
__global__ __launch_bounds__(256) void tgemm_kernel(
    const float* __restrict__ A, int lda,
    const float* __restrict__ Bm, int ldb, int bpermB,
    float* __restrict__ C, int ldc,
    int M, int N, int K,
    const float* __restrict__ bias,
    const float* __restrict__ bias2,
    const float* __restrict__ res, int ldres,
    int relu,
    float* __restrict__ hout,
    __half* __restrict__ gqh)
{
    extern __shared__ float sm[];
    float* sAh = sm;
    float* sBh = sm + 128 * SMS;

    const int tid = threadIdx.x;
    const int bm = blockIdx.y * 128;
    const int bn = blockIdx.x * 128;
    const int wid = tid >> 5, lane = tid & 31;
    const int wm = (wid >> 2) * 64, wn = (wid & 3) * 32;
    const int gr = lane >> 2, gc = lane & 3;
    const int lrow = tid >> 3;
    const int lcol = (tid & 7) * 4;

    float acc[4][4][4];
#pragma unroll
    for (int i = 0; i < 4; i++)
#pragma unroll
        for (int j = 0; j < 4; j++)
#pragma unroll
            for (int k = 0; k < 4; k++) acc[i][j][k] = 0.f;

    // B row source indices (permuted once)
    int bsrc[4];
#pragma unroll
    for (int p = 0; p < 4; p++) {
        int n = bn + p * 32 + lrow;
        bsrc[p] = bpermB ? lstm_perm(n) : n;
    }

    float4 pva[4], pvb[4];
    const bool avalid[4] = { bm + 0 * 32 + lrow < M, bm + 1 * 32 + lrow < M,
                             bm + 2 * 32 + lrow < M, bm + 3 * 32 + lrow < M };

#pragma unroll
    for (int p = 0; p < 4; p++) {
        int row = p * 32 + lrow;
        pva[p] = avalid[p] ? *(const float4*)(A + (size_t)(bm + row) * lda + lcol)
                           : make_float4(0.f, 0.f, 0.f, 0.f);
        pvb[p] = *(const float4*)(Bm + (size_t)bsrc[p] * ldb + lcol);
    }

    for (int k0 = 0; k0 < K; k0 += 32) {
#pragma unroll
        for (int p = 0; p < 4; p++) {
            int row = p * 32 + lrow;
            float av[4] = {pva[p].x, pva[p].y, pva[p].z, pva[p].w};
            float bv[4] = {pvb[p].x, pvb[p].y, pvb[p].z, pvb[p].w};
#pragma unroll
            for (int i = 0; i < 4; i++) {
                sAh[row * SMS + lcol + i] = __uint_as_float(f2tf32(av[i]));
                sBh[row * SMS + lcol + i] = __uint_as_float(f2tf32(bv[i]));
            }
        }
        __syncthreads();

        if (k0 + 32 < K) {
#pragma unroll
            for (int p = 0; p < 4; p++) {
                int row = p * 32 + lrow;
                pva[p] = avalid[p] ? *(const float4*)(A + (size_t)(bm + row) * lda + k0 + 32 + lcol)
                                   : make_float4(0.f, 0.f, 0.f, 0.f);
                pvb[p] = *(const float4*)(Bm + (size_t)bsrc[p] * ldb + k0 + 32 + lcol);
            }
        }

#pragma unroll
        for (int ks = 0; ks < 4; ks++) {
            int kb = ks * 8;
            uint32_t ah[4][4], bh[4][2];
#pragma unroll
            for (int mi = 0; mi < 4; mi++) {
                int base = (wm + mi * 16 + gr) * SMS + kb + gc;
                ah[mi][0] = __float_as_uint(sAh[base]);
                ah[mi][1] = __float_as_uint(sAh[base + 8 * SMS]);
                ah[mi][2] = __float_as_uint(sAh[base + 4]);
                ah[mi][3] = __float_as_uint(sAh[base + 8 * SMS + 4]);
            }
#pragma unroll
            for (int ni = 0; ni < 4; ni++) {
                int base = (wn + ni * 8 + gr) * SMS + kb + gc;
                bh[ni][0] = __float_as_uint(sBh[base]);
                bh[ni][1] = __float_as_uint(sBh[base + 4]);
            }
#pragma unroll
            for (int mi = 0; mi < 4; mi++)
#pragma unroll
                for (int ni = 0; ni < 4; ni++)
                    MMA_TF32(acc[mi][ni], ah[mi], bh[ni]);
        }
        __syncthreads();
    }

    // Epilogue
#pragma unroll
    for (int mi = 0; mi < 4; mi++) {
#pragma unroll
        for (int ni = 0; ni < 4; ni++) {
            int col = bn + wn + ni * 8 + gc * 2;
            float b0, b1;
            if (EPI == 1) {
                int j0 = lstm_perm(col), j1 = lstm_perm(col + 1);
                b0 = bias[j0] + bias2[j0];
                b1 = bias[j1] + bias2[j1];
            } else {
                b0 = bias ? bias[col] : 0.f;
                b1 = bias ? bias[col + 1] : 0.f;
            }
            float v[4];
#pragma unroll
            for (int half_ = 0; half_ < 2; half_++) {
                int r = bm + wm + mi * 16 + gr + half_ * 8;
                float x0 = acc[mi][ni][half_ * 2 + 0] + b0;
                float x1 = acc[mi][ni][half_ * 2 + 1] + b1;
                if (EPI == 0) {
                    if (res && r < M) {
                        x0 += res[(size_t)r * ldres + col];
                        x1 += res[(size_t)r * ldres + col + 1];
                    }
                    if (r < M) {
                        float y0 = relu ? fmaxf(x0, 0.f) : x0;
                        float y1 = relu ? fmaxf(x1, 0.f) : x1;
                        C[(size_t)r * ldc + col]     = y0;
                        C[(size_t)r * ldc + col + 1] = y1;
                    }
                } else if (EPI == 1) {
                    *(__half2*)(gqh + (size_t)r * 1024 + col) = __floats2half2_rn(x0, x1);
                } else {  // EPI == 2
                    __half2 hg = *(const __half2*)(gqh + (size_t)r * 1024 + col);
                    x0 += __half2float(__low2half(hg));
                    x1 += __half2float(__high2half(hg));
                }
                v[half_ * 2 + 0] = x0;
                v[half_ * 2 + 1] = x1;
            }
            if (EPI != 0) {
                float p0 = __shfl_xor_sync(~0u, v[0], 1);
                float p1 = __shfl_xor_sync(~0u, v[1], 1);
                float p2 = __shfl_xor_sync(~0u, v[2], 1);
                float p3 = __shfl_xor_sync(~0u, v[3], 1);
                if (!(gc & 1)) {
                    int u = col >> 2;
#pragma unroll
                    for (int half_ = 0; half_ < 2; half_++) {
                        int r = bm + wm + mi * 16 + gr + half_ * 8;
                        float gi = v[half_ * 2], gf = v[half_ * 2 + 1];
                        float gg = half_ ? p2 : p0;
                        float go = half_ ? p3 : p1;
                        float cp = (EPI == 1) ? 0.f : g_c[(size_t)r * 256 + u];
                        float cn = fast_sig(gf) * cp + fast_sig(gi) * fast_tanh(gg);
                        g_c[(size_t)r * 256 + u] = cn;
                        hout[(size_t)r * 256 + u] =
                            g_X[(size_t)r * 256 + u] + fast_sig(go) * fast_tanh(cn);
                    }
                }
            }
        }
    }
}

// ---------------------------------------------------------------------------
// bf16x3 GEMM for the P table (register prefetch, single buffer).
// B operand read directly from gcn_w_W (128x256) via folded transpose:
//   row n, col k  <-  W[n & 127][(n >> 7) * 128 + k]
// ---------------------------------------------------------------------------
#define BSMS 20
__device__ __forceinline__ void packbf(float f0, float f1, uint32_t& hi, uint32_t& lo)
{
    __nv_bfloat162 h = __floats2bfloat162_rn(f0, f1);
    float r0 = __bfloat162float(h.x), r1 = __bfloat162float(h.y);
    __nv_bfloat162 l = __floats2bfloat162_rn(f0 - r0, f1 - r1);
    hi = *reinterpret_cast<uint32_t*>(&h);
    lo = *reinterpret_cast<uint32_t*>(&l);
}

__global__ __launch_bounds__(256) void bgemm_kernel(
    const float* __restrict__ A, int lda,
    const float* __restrict__ W,   // gcn_w_W, 128 x 256
    float* __restrict__ C, int ldc,
    int M, int N, int K)
{
    extern __shared__ uint32_t smu[];
    uint32_t* sAh = smu;
    uint32_t* sAl = smu + 128 * BSMS;
    uint32_t* sBh = smu + 2 * 128 * BSMS;
    uint32_t* sBl = smu + 3 * 128 * BSMS;

    const int tid = threadIdx.x;
    const int bm = blockIdx.y * 128;
    const int bn = blockIdx.x * 128;
    const int wid = tid >> 5, lane = tid & 31;
    const int wm = (wid >> 2) * 64, wn = (wid & 3) * 32;
    const int gr = lane >> 2, gc = lane & 3;
    const int lrow = tid >> 3;
    const int kp0 = (tid & 7) * 2;

    float acc[4][4][4];
#pragma unroll
    for (int i = 0; i < 4; i++)
#pragma unroll
        for (int j = 0; j < 4; j++)
#pragma unroll
            for (int k = 0; k < 4; k++) acc[i][j][k] = 0.f;

    // folded B row base pointers
    const float* bptr[4];
#pragma unroll
    for (int p = 0; p < 4; p++) {
        int n = bn + p * 32 + lrow;
        bptr[p] = W + (size_t)(n & 127) * 256 + ((n >> 7) << 7);
    }

    float4 pva[4], pvb[4];
    const bool avalid[4] = { bm + 0 * 32 + lrow < M, bm + 1 * 32 + lrow < M,
                             bm + 2 * 32 + lrow < M, bm + 3 * 32 + lrow < M };
#pragma unroll
    for (int p = 0; p < 4; p++) {
        int row = p * 32 + lrow;
        pva[p] = avalid[p] ? *(const float4*)(A + (size_t)(bm + row) * lda + kp0 * 2)
                           : make_float4(0.f, 0.f, 0.f, 0.f);
        pvb[p] = *(const float4*)(bptr[p] + kp0 * 2);
    }

    for (int k0 = 0; k0 < K; k0 += 32) {
#pragma unroll
        for (int p = 0; p < 4; p++) {
            int row = p * 32 + lrow;
            uint32_t h, l;
            packbf(pva[p].x, pva[p].y, h, l); sAh[row * BSMS + kp0] = h;     sAl[row * BSMS + kp0] = l;
            packbf(pva[p].z, pva[p].w, h, l); sAh[row * BSMS + kp0 + 1] = h; sAl[row * BSMS + kp0 + 1] = l;
            packbf(pvb[p].x, pvb[p].y, h, l); sBh[row * BSMS + kp0] = h;     sBl[row * BSMS + kp0] = l;
            packbf(pvb[p].z, pvb[p].w, h, l); sBh[row * BSMS + kp0 + 1] = h; sBl[row * BSMS + kp0 + 1] = l;
        }
        __syncthreads();

        if (k0 + 32 < K) {
#pragma unroll
            for (int p = 0; p < 4; p++) {
                int row = p * 32 + lrow;
                pva[p] = avalid[p] ? *(const float4*)(A + (size_t)(bm + row) * lda + k0 + 32 + kp0 * 2)
                                   : make_float4(0.f, 0.f, 0.f, 0.f);
                pvb[p] = *(const float4*)(bptr[p] + k0 + 32 + kp0 * 2);
            }
        }

#pragma unroll
        for (int kb = 0; kb < 2; kb++) {
            uint32_t ah[4][4], al[4][4], bh[4][2], bl[4][2];
#pragma unroll
            for (int mi = 0; mi < 4; mi++) {
                int base = (wm + mi * 16 + gr) * BSMS + kb * 8 + gc;
                ah[mi][0] = sAh[base];
                ah[mi][1] = sAh[base + 8 * BSMS];
                ah[mi][2] = sAh[base + 4];
                ah[mi][3] = sAh[base + 8 * BSMS + 4];
                al[mi][0] = sAl[base];
                al[mi][1] = sAl[base + 8 * BSMS];
                al[mi][2] = sAl[base + 4];
                al[mi][3] = sAl[base + 8 * BSMS + 4];
            }
#pragma unroll
            for (int ni = 0; ni < 4; ni++) {
                int base = (wn + ni * 8 + gr) * BSMS + kb * 8 + gc;
                bh[ni][0] = sBh[base];
                bh[ni][1] = sBh[base + 4];
                bl[ni][0] = sBl[base];
                bl[ni][1] = sBl[base + 4];
            }
#pragma unroll
            for (int mi = 0; mi < 4; mi++)
#pragma unroll
                for (int ni = 0; ni < 4; ni++) {
                    MMA_BF16(acc[mi][ni], ah[mi], bh[ni]);
                    MMA_BF16(acc[mi][ni], ah[mi], bl[ni]);
                    MMA_BF16(acc[mi][ni], al[mi], bh[ni]);
                }
        }
        __syncthreads();
    }

#pragma unroll
    for (int mi = 0; mi < 4; mi++)
#pragma unroll
        for (int ni = 0; ni < 4; ni++) {
            int col = bn + wn + ni * 8 + gc * 2;
#pragma unroll
            for (int half_ = 0; half_ < 2; half_++) {
                int r = bm + wm + mi * 16 + gr + half_ * 8;
                if (r < M) {
                    C[(size_t)r * ldc + col]     = acc[mi][ni][half_ * 2 + 0];
                    C[(size_t)r * ldc + col + 1] = acc[mi][ni][half_ * 2 + 1];
                }
            }
        }
}

// whhr[j] = dot(g_sg, Whh[jm, 256:512])
__global__ void prep_whhr_kernel(const float* __restrict__ Whh)
{
    int j = blockIdx.x;
    int jm = lstm_perm(j);
    int t = threadIdx.x;
    float p = g_sg[t] * Whh[jm * 512 + 256 + t];
    __shared__ float red[8];
    for (int o = 16; o > 0; o >>= 1) p += __shfl_xor_sync(~0u, p, o);
    if ((t & 31) == 0) red[t >> 5] = p;
    __syncthreads();
    if (t == 0) {
        float s = 0.f;
        for (int i = 0; i < 8; i++) s += red[i];
        g_whhr[j] = s;
    }
}

// ---------------------------------------------------------------------------
// Neighbor encoder: one block (256 thr, 8 warps) per entity. 8202 entities.
// ---------------------------------------------------------------------------
__global__ __launch_bounds__(256) void neighbor_kernel(
                                const int* __restrict__ query,
                                const int* __restrict__ support,
                                const int* __restrict__ q_l1, const int* __restrict__ q_deg_l,
                                const int* __restrict__ q_r1, const int* __restrict__ q_deg_r,
                                const int* __restrict__ s_l1, const int* __restrict__ s_deg_l,
                                const int* __restrict__ s_r1, const int* __restrict__ s_deg_r,
                                const float* __restrict__ sym,
                                const float* __restrict__ gwb, const float* __restrict__ gb,
                                const float* __restrict__ gate_w,
                                const float* __restrict__ gate_temp)
{
    __shared__ __align__(16) float s_self[128], s_bias[128];
    __shared__ __align__(16) float s_proj[MAXK][128];
    __shared__ int   s_conn[2 * MAXK];
    __shared__ float s_cos[MAXK];
    __shared__ float s_gw[MAXK];
    __shared__ int   s_sel[KNEI];
    __shared__ float s_scal[2];

    int e = blockIdx.x;
    const int* conn; int sid, deg; float* outp;
    if (e < 4096)      { conn = q_l1 + e * 100;                sid = query[e * 2];           deg = q_deg_l[e];      outp = g_qvec + e * 256; }
    else if (e < 8192) { int i = e - 4096; conn = q_r1 + i * 100; sid = query[i * 2 + 1];   deg = q_deg_r[i];      outp = g_qvec + i * 256 + 128; }
    else if (e < 8197) { int i = e - 8192; conn = s_l1 + i * 100; sid = support[i * 2];     deg = s_deg_l[i];      outp = g_svec + i * 256; }
    else               { int i = e - 8197; conn = s_r1 + i * 100; sid = support[i * 2 + 1]; deg = s_deg_r[i];      outp = g_svec + i * 256 + 128; }

    int t = threadIdx.x, lane = t & 31, w = t >> 5;
    if (t < 128) {
        s_self[t] = sym[(size_t)sid * 128 + t];
        s_bias[t] = gwb[t] + gb[t];
    } else if (t - 128 < 2 * MAXK) {
        s_conn[t - 128] = conn[t - 128];
    }
    __syncthreads();

    if (w == 0) {
        float ss = 0.f;
#pragma unroll
        for (int i = 0; i < 4; i++) { float v = s_self[lane + 32 * i]; ss += v * v; }
        for (int o = 16; o > 0; o >>= 1) ss += __shfl_xor_sync(~0u, ss, o);
        if (lane == 0) s_scal[0] = sqrtf(ss + EPS);
    } else if (w == 1) {
        if (lane < MAXK) { int r = s_conn[2 * lane]; s_gw[lane] = gate_w[(r == PADID) ? 0 : r]; }
    } else if (w == 2) {
        if (lane + 32 < MAXK) { int r = s_conn[2 * (lane + 32)]; s_gw[lane + 32] = gate_w[(r == PADID) ? 0 : r]; }
    }
    __syncthreads();
    float nself = s_scal[0];

    const float4* self4 = (const float4*)s_self;
    const float4* bias4 = (const float4*)s_bias;
    float4 sf = self4[lane];
    float4 bf = bias4[lane];

#pragma unroll
    for (int it = 0; it < 7; it++) {
        int n = it * 8 + w;
        if (n < MAXK) {
            int rel = s_conn[2 * n], ent = s_conn[2 * n + 1];
            float4 a = ((const float4*)(g_P + (size_t)rel * 256))[lane];
            float4 bb = ((const float4*)(g_P + (size_t)ent * 256 + 128))[lane];
            float va[4] = {a.x + bb.x + bf.x, a.y + bb.y + bf.y,
                           a.z + bb.z + bf.z, a.w + bb.w + bf.w};
            float sfv[4] = {sf.x, sf.y, sf.z, sf.w};
            float dp = 0.f, nn = 0.f;
            float4 pv;
#pragma unroll
            for (int i = 0; i < 4; i++) {
                float v = va[i];
                v = (v > 0.f) ? v : 0.01f * v;
                if (rel == PADID) v = 0.f;
                (&pv.x)[i] = v;
                dp += sfv[i] * v;
                nn += v * v;
            }
            ((float4*)s_proj[n])[lane] = pv;
            for (int o = 16; o > 0; o >>= 1) {
                dp += __shfl_xor_sync(~0u, dp, o);
                nn += __shfl_xor_sync(~0u, nn, o);
            }
            if (lane == 0) {
                float nnei = sqrtf(nn + EPS);
                s_cos[n] = dp / (nself * nnei + EPS);
            }
        }
    }
    __syncthreads();

    if (w == 0) {
        float v0 = s_cos[lane];
        float v1 = (lane + 32 < MAXK) ? s_cos[lane + 32] : -3.0e38f;
#pragma unroll
        for (int k = 0; k < KNEI; k++) {
            float bv = v0; int bi = lane;
            if (v1 > bv) { bv = v1; bi = lane + 32; }
            for (int o = 16; o > 0; o >>= 1) {
                float ov = __shfl_xor_sync(~0u, bv, o);
                int   oi = __shfl_xor_sync(~0u, bi, o);
                if (ov > bv || (ov == bv && oi < bi)) { bv = ov; bi = oi; }
            }
            if (lane == 0) s_sel[k] = bi;
            if (bi == lane) v0 = -3.0e38f;
            else if (bi == lane + 32) v1 = -3.0e38f;
        }
    } else if (w == 1) {
        float gv = s_gw[lane];
        gv += (lane + 32 < MAXK) ? s_gw[lane + 32] : 0.f;
        for (int o = 16; o > 0; o >>= 1) gv += __shfl_xor_sync(~0u, gv, o);
        if (lane == 0) {
            float gate = fast_sig((gv / 50.f) / gate_temp[0]);
            if (deg <= 0) gate = 1.f;
            s_scal[1] = gate;
        }
    }
    __syncthreads();

    if (t < 128) {
        float agg = 0.f;
#pragma unroll
        for (int k = 0; k < KNEI; k++) agg += s_proj[s_sel[k]][t];
        agg /= 10.f;
        outp[t] = fast_tanh(s_self[t] + s_scal[1] * agg);
    }
}

// ---------------------------------------------------------------------------
// Fused support encoder: one block per support row (grid=FEW, 1024 threads).
// stage1 MLP1 -> stage2 MLP2+res -> LN -> writes g_sh[r][:] (normalized+affine)
// ---------------------------------------------------------------------------
__global__ __launch_bounds__(1024) void seA_kernel(
    const float* __restrict__ W1, const float* __restrict__ b1,
    const float* __restrict__ W2, const float* __restrict__ b2,
    const float* __restrict__ g,  const float* __restrict__ b)
{
    __shared__ __align__(16) float sx[256];
    __shared__ __align__(16) float sh1[512];
    __shared__ float shs[256];
    __shared__ float red[32];
    __shared__ float s_mu, s_rs;

    int r = blockIdx.x;
    int t = threadIdx.x, lane = t & 31, w = t >> 5;   // 32 warps

    if (t < 256) sx[t] = g_svec[r * 256 + t];
    __syncthreads();

    // stage 1: sh1[j] = relu(sx . W1[j] + b1[j]), 512 outputs, warp-per-output
    const float4* x4 = (const float4*)sx;
#pragma unroll
    for (int it = 0; it < 16; it++) {
        int j = it * 32 + w;
        const float4* w4 = (const float4*)(W1 + (size_t)j * 256);
        float acc = 0.f;
#pragma unroll
        for (int k = lane; k < 64; k += 32) {
            float4 xv = x4[k], wv = w4[k];
            acc = fmaf(xv.x, wv.x, acc); acc = fmaf(xv.y, wv.y, acc);
            acc = fmaf(xv.z, wv.z, acc); acc = fmaf(xv.w, wv.w, acc);
        }
        for (int o = 16; o > 0; o >>= 1) acc += __shfl_xor_sync(~0u, acc, o);
        if (lane == 0) sh1[j] = fmaxf(acc + b1[j], 0.f);
    }
    __syncthreads();

    // stage 2: shs[c] = sh1 . W2[c] + b2[c] + sx[c], 256 outputs
    const float4* h4 = (const float4*)sh1;
#pragma unroll
    for (int it = 0; it < 8; it++) {
        int c = it * 32 + w;
        const float4* w4 = (const float4*)(W2 + (size_t)c * 512);
        float acc = 0.f;
#pragma unroll
        for (int k = lane; k < 128; k += 32) {
            float4 xv = h4[k], wv = w4[k];
            acc = fmaf(xv.x, wv.x, acc); acc = fmaf(xv.y, wv.y, acc);
            acc = fmaf(xv.z, wv.z, acc); acc = fmaf(xv.w, wv.w, acc);
        }
        for (int o = 16; o > 0; o >>= 1) acc += __shfl_xor_sync(~0u, acc, o);
        if (lane == 0) shs[c] = acc + b2[c] + sx[c];
    }
    __syncthreads();

    // LN over shs (first 256 threads)
    if (t < 256) {
        float v = shs[t];
        float s = v;
        for (int o = 16; o > 0; o >>= 1) s += __shfl_xor_sync(~0u, s, o);
        if (lane == 0) red[w] = s;
    }
    __syncthreads();
    if (t == 0) { float m = 0.f; for (int i = 0; i < 8; i++) m += red[i]; s_mu = m / 256.f; }
    __syncthreads();
    if (t < 256) {
        float d = shs[t] - s_mu;
        float q = d * d;
        for (int o = 16; o > 0; o >>= 1) q += __shfl_xor_sync(~0u, q, o);
        if (lane == 0) red[w] = q;
    }
    __syncthreads();
    if (t == 0) { float m = 0.f; for (int i = 0; i < 8; i++) m += red[i]; s_rs = 1.f / sqrtf(m / 256.f + LNEPS); }
    __syncthreads();
    if (t < 256)
        g_sh[r * 256 + t] = g[t] * (shs[t] - s_mu) * s_rs + b[t];
}

// mean of LN'd rows -> g_sg, plus its norm -> g_sgn
__global__ void se3b_kernel()
{
    __shared__ float red[8];
    int t = threadIdx.x, lane = t & 31, w = t >> 5;
    float acc = 0.f;
#pragma unroll
    for (int r = 0; r < FEW; r++) acc += g_sh[r * 256 + t];
    acc *= 0.2f;
    g_sg[t] = acc;
    float nq = acc * acc;
    for (int o = 16; o > 0; o >>= 1) nq += __shfl_xor_sync(~0u, nq, o);
    if (lane == 0) red[w] = nq;
    __syncthreads();
    if (t == 0) {
        float s = 0.f;
        for (int i = 0; i < 8; i++) s += red[i];
        g_sgn[0] = sqrtf(s + EPS);
    }
}

// ---------------------------------------------------------------------------
// LayerNorm rows of g_tmp -> g_X
// ---------------------------------------------------------------------------
__global__ void ln_kernel(const float* __restrict__ g, const float* __restrict__ b)
{
    int row = blockIdx.x, t = threadIdx.x;
    float v = g_tmp[(size_t)row * 256 + t];
    __shared__ float red[8];
    __shared__ float s_mu, s_rs;
    float s = v;
    for (int o = 16; o > 0; o >>= 1) s += __shfl_xor_sync(~0u, s, o);
    if ((t & 31) == 0) red[t >> 5] = s;
    __syncthreads();
    if (t == 0) { float m = 0.f; for (int i = 0; i < 8; i++) m += red[i]; s_mu = m / 256.f; }
    __syncthreads();
    float d = v - s_mu;
    float q = d * d;
    for (int o = 16; o > 0; o >>= 1) q += __shfl_xor_sync(~0u, q, o);
    if ((t & 31) == 0) red[t >> 5] = q;
    __syncthreads();
    if (t == 0) { float m = 0.f; for (int i = 0; i < 8; i++) m += red[i]; s_rs = 1.f / sqrtf(m / 256.f + LNEPS); }
    __syncthreads();
    g_X[(size_t)row * 256 + t] = g[t] * d * s_rs + b[t];
}

// ---------------------------------------------------------------------------
// Final cosine vs support_g
// ---------------------------------------------------------------------------
__global__ void final_kernel(const float* __restrict__ h_in, float* __restrict__ out)
{
    __shared__ float ssg[256];
    int t = threadIdx.x, lane = t & 31, w = t >> 5;
    ssg[t] = g_sg[t];
    __syncthreads();
    int row = blockIdx.x * 8 + w;
    const float* h = h_in + (size_t)row * 256;
    float dp = 0.f, nq = 0.f;
#pragma unroll
    for (int i = 0; i < 8; i++) {
        int d = lane + 32 * i;
        float v = h[d];
        dp += v * ssg[d];
        nq += v * v;
    }
    for (int o = 16; o > 0; o >>= 1) {
        dp += __shfl_xor_sync(~0u, dp, o);
        nq += __shfl_xor_sync(~0u, nq, o);
    }
    if (lane == 0) out[row] = dp / (sqrtf(nq + EPS) * g_sgn[0]);
}

// ---------------------------------------------------------------------------
// kernel_launch (single stream)
// ---------------------------------------------------------------------------
extern "C" void kernel_launch(void* const* d_in, const int* in_sizes, int n_in,
                              void* d_out, int out_size)
{
    const int*   query     = (const int*)d_in[0];
    const int*   support   = (const int*)d_in[1];
    const int*   q_l1      = (const int*)d_in[2];
    const int*   q_deg_l   = (const int*)d_in[3];
    const int*   q_r1      = (const int*)d_in[4];
    const int*   q_deg_r   = (const int*)d_in[5];
    const int*   s_l1      = (const int*)d_in[6];
    const int*   s_deg_l   = (const int*)d_in[7];
    const int*   s_r1      = (const int*)d_in[8];
    const int*   s_deg_r   = (const int*)d_in[9];
    const float* sym       = (const float*)d_in[10];
    const float* gcn_w_W   = (const float*)d_in[11];
    const float* gcn_w_b   = (const float*)d_in[12];
    const float* gcn_b     = (const float*)d_in[13];
    const float* gate_w    = (const float*)d_in[14];
    const float* gate_temp = (const float*)d_in[15];
    const float* se_W1     = (const float*)d_in[16];
    const float* se_b1     = (const float*)d_in[17];
    const float* se_W2     = (const float*)d_in[18];
    const float* se_b2     = (const float*)d_in[19];
    const float* ln_g      = (const float*)d_in[20];
    const float* ln_b      = (const float*)d_in[21];
    const float* lstm_Wih  = (const float*)d_in[22];
    const float* lstm_Whh  = (const float*)d_in[23];
    const float* lstm_bih  = (const float*)d_in[24];
    const float* lstm_bhh  = (const float*)d_in[25];
    float* out = (float*)d_out;

    float *pP, *pQv, *pH1, *pTmp, *pX, *pWhhr, *pH, *pH2;
    __half* pGq;
    cudaGetSymbolAddress((void**)&pP,     g_P);
    cudaGetSymbolAddress((void**)&pQv,    g_qvec);
    cudaGetSymbolAddress((void**)&pH1,    g_H1);
    cudaGetSymbolAddress((void**)&pTmp,   g_tmp);
    cudaGetSymbolAddress((void**)&pX,     g_X);
    cudaGetSymbolAddress((void**)&pWhhr,  g_whhr);
    cudaGetSymbolAddress((void**)&pGq,    g_Gq);
    cudaGetSymbolAddress((void**)&pH,     g_h);
    cudaGetSymbolAddress((void**)&pH2,    g_h2);

    const int SM_T = 2 * 128 * SMS * (int)sizeof(float);     // 36864
    const int SM_B = 4 * 128 * BSMS * (int)sizeof(uint32_t); // 40960
    static int attr_done = 0;
    if (!attr_done) {
        cudaFuncSetAttribute(tgemm_kernel<0>, cudaFuncAttributeMaxDynamicSharedMemorySize, SM_T);
        cudaFuncSetAttribute(tgemm_kernel<1>, cudaFuncAttributeMaxDynamicSharedMemorySize, SM_T);
        cudaFuncSetAttribute(tgemm_kernel<2>, cudaFuncAttributeMaxDynamicSharedMemorySize, SM_T);
        cudaFuncSetAttribute(bgemm_kernel,    cudaFuncAttributeMaxDynamicSharedMemorySize, SM_B);
        attr_done = 1;
    }

    // 1) P = sym_emb @ Wt^T  (bf16x3; Wt folded from gcn_w_W)
    bgemm_kernel<<<dim3(2, (NSYM + 1 + 127) / 128), 256, SM_B>>>(
        sym, 128, gcn_w_W, pP, 256, NSYM + 1, 256, 128);

    // 2) neighbor encoder -> g_qvec, g_svec
    neighbor_kernel<<<8202, 256>>>(query, support, q_l1, q_deg_l, q_r1, q_deg_r,
                                   s_l1, s_deg_l, s_r1, s_deg_r,
                                   sym, gcn_w_b, gcn_b, gate_w, gate_temp);

    // 3) query SE GEMM 1
    tgemm_kernel<0><<<dim3(4, 32), 256, SM_T>>>(pQv, 256, se_W1, 256, 0, pH1, 512,
                                                B, 512, 256, se_b1, nullptr, nullptr, 0, 1,
                                                nullptr, nullptr);

    // 4) fused support encoder (per-row MLP+LN)
    seA_kernel<<<FEW, 1024>>>(se_W1, se_b1, se_W2, se_b2, ln_g, ln_b);

    // 5-6) support mean/norm, whhr
    se3b_kernel<<<1, 256>>>();
    prep_whhr_kernel<<<1024, 256>>>(lstm_Whh);

    // 7-8) query SE GEMM 2 + LN
    tgemm_kernel<0><<<dim3(2, 32), 256, SM_T>>>(pH1, 512, se_W2, 512, 0, pTmp, 256,
                                                B, 256, 512, se_b2, nullptr, pQv, 256, 0,
                                                nullptr, nullptr);
    ln_kernel<<<B, 256>>>(ln_g, ln_b);

    // 9) Gq = X @ Wih^T (perm) + (bih+bhh); fused LSTM step 1 -> h in g_h
    tgemm_kernel<1><<<dim3(8, 32), 256, SM_T>>>(pX, 256, lstm_Wih, 256, 1, nullptr, 0,
                                                B, 1024, 256, lstm_bih, lstm_bhh, nullptr, 0, 0,
                                                pH, pGq);

    // 10-12) LSTM steps 2..4 (WhhL read via perm from lstm_Whh, ldb=512)
    tgemm_kernel<2><<<dim3(8, 32), 256, SM_T>>>(pH, 256, lstm_Whh, 512, 1, nullptr, 0,
                                                B, 1024, 256, pWhhr, nullptr, nullptr, 0, 0,
                                                pH2, pGq);
    tgemm_kernel<2><<<dim3(8, 32), 256, SM_T>>>(pH2, 256, lstm_Whh, 512, 1, nullptr, 0,
                                                B, 1024, 256, pWhhr, nullptr, nullptr, 0, 0,
                                                pH, pGq);
    tgemm_kernel<2><<<dim3(8, 32), 256, SM_T>>>(pH, 256, lstm_Whh, 512, 1, nullptr, 0,
                                                B, 1024, 256, pWhhr, nullptr, nullptr, 0, 0,
                                                pH2, pGq);

    // 13) final cosine
    final_kernel<<<B / 8, 256>>>(pH2, out);
}

// round 13
// speedup vs baseline: 1.0149x; 1.0149x over previous
#include <cuda_runtime.h>
#include <cuda_bf16.h>
#include <cuda_fp16.h>
#include <math.h>
#include <stdint.h>

#define NSYM   100000
#define PADID  100000
#define B      4096
#define FEW    5
#define MAXK   50
#define KNEI   10
#define EPS    1e-8f
#define LNEPS  1e-5f

// ---------------------------------------------------------------------------
// Scratch (device globals -- no allocations allowed)
// ---------------------------------------------------------------------------
__device__ __align__(128) float g_P[(NSYM + 1) * 256];
__device__ __align__(128) float g_Wt[256 * 128];
__device__ __align__(128) float g_qvec[B * 256];
__device__ __align__(128) float g_svec[FEW * 256];
__device__ __align__(128) float g_sh1[FEW * 512];
__device__ __align__(128) float g_sh[FEW * 256];
__device__ __align__(128) float g_sg[256];
__device__ __align__(128) float g_sgn[1];
__device__ __align__(128) float g_H1[B * 512];
__device__ __align__(128) float g_tmp[B * 256];
__device__ __align__(128) float g_X[B * 256];
__device__ __align__(128) float g_Wihp[1024 * 256];
__device__ __align__(128) float g_WhhLp[1024 * 256];
__device__ __align__(128) float g_bsum[1024];
__device__ __align__(128) float g_whhr[1024];
__device__ __align__(128) __half g_Gq[B * 1024];
__device__ __align__(128) float g_c[B * 256];
__device__ __align__(128) float g_h[B * 256];
__device__ __align__(128) float g_h2[B * 256];

__device__ __forceinline__ float fast_tanh(float x) {
    float y;
    asm("tanh.approx.f32 %0, %1;" : "=f"(y) : "f"(x));
    return y;
}
__device__ __forceinline__ float fast_sig(float x) {
    return 0.5f * fast_tanh(0.5f * x) + 0.5f;
}

__device__ __forceinline__ uint32_t f2tf32(float x) {
    uint32_t r;
    asm("cvt.rna.tf32.f32 %0, %1;" : "=r"(r) : "f"(x));
    return r;
}

#define MMA_TF32(d, a, b)                                                     \
    asm volatile("mma.sync.aligned.m16n8k8.row.col.f32.tf32.tf32.f32 "        \
                 "{%0,%1,%2,%3}, {%4,%5,%6,%7}, {%8,%9}, {%0,%1,%2,%3};"      \
                 : "+f"(d[0]), "+f"(d[1]), "+f"(d[2]), "+f"(d[3])             \
                 : "r"(a[0]), "r"(a[1]), "r"(a[2]), "r"(a[3]),                \
                   "r"(b[0]), "r"(b[1]))

#define MMA_BF16(d, a, b)                                                     \
    asm volatile("mma.sync.aligned.m16n8k16.row.col.f32.bf16.bf16.f32 "       \
                 "{%0,%1,%2,%3}, {%4,%5,%6,%7}, {%8,%9}, {%0,%1,%2,%3};"      \
                 : "+f"(d[0]), "+f"(d[1]), "+f"(d[2]), "+f"(d[3])             \
                 : "r"(a[0]), "r"(a[1]), "r"(a[2]), "r"(a[3]),                \
                   "r"(b[0]), "r"(b[1]))

// ---------------------------------------------------------------------------
// TF32 tensor-core GEMM with register prefetch (single smem buffer).
// __launch_bounds__(256, 2): force 2 blocks/SM (regs were 124 <= 128 cap).
// C[M,N] = A[M,K] @ B[N,K]^T (+bias[n]) (+res) (relu?)
// BM=BN=128, BK=32, 256 threads (8 warps, 2x4), warp tile 64x32.
// EPI=0: generic. EPI=1: LSTM step 1 (fp16 gate store). EPI=2: LSTM steps 2-4.
// ---------------------------------------------------------------------------
#define SMS 36
template <int EPI>
__global__ __launch_bounds__(256, 2) void tgemm_kernel(
    const float* __restrict__ A, int lda,
    const float* __restrict__ Bm, int ldb,
    float* __restrict__ C, int ldc,
    int M, int N, int K,
    const float* __restrict__ bias,
    const float* __restrict__ res, int ldres,
    int relu,
    float* __restrict__ hout,
    __half* __restrict__ gqh)
{
    extern __shared__ float sm[];
    float* sAh = sm;
    float* sBh = sm + 128 * SMS;

    const int tid = threadIdx.x;
    const int bm = blockIdx.y * 128;
    const int bn = blockIdx.x * 128;
    const int wid = tid >> 5, lane = tid & 31;
    const int wm = (wid >> 2) * 64, wn = (wid & 3) * 32;
    const int gr = lane >> 2, gc = lane & 3;
    const int lrow = tid >> 3;
    const int lcol = (tid & 7) * 4;

    float acc[4][4][4];
#pragma unroll
    for (int i = 0; i < 4; i++)
#pragma unroll
        for (int j = 0; j < 4; j++)
#pragma unroll
            for (int k = 0; k < 4; k++) acc[i][j][k] = 0.f;

    float4 pva[4], pvb[4];
    const bool avalid[4] = { bm + 0 * 32 + lrow < M, bm + 1 * 32 + lrow < M,
                             bm + 2 * 32 + lrow < M, bm + 3 * 32 + lrow < M };

#pragma unroll
    for (int p = 0; p < 4; p++) {
        int row = p * 32 + lrow;
        pva[p] = avalid[p] ? *(const float4*)(A + (size_t)(bm + row) * lda + lcol)
                           : make_float4(0.f, 0.f, 0.f, 0.f);
        pvb[p] = *(const float4*)(Bm + (size_t)(bn + row) * ldb + lcol);
    }

    for (int k0 = 0; k0 < K; k0 += 32) {
#pragma unroll
        for (int p = 0; p < 4; p++) {
            int row = p * 32 + lrow;
            float av[4] = {pva[p].x, pva[p].y, pva[p].z, pva[p].w};
            float bv[4] = {pvb[p].x, pvb[p].y, pvb[p].z, pvb[p].w};
#pragma unroll
            for (int i = 0; i < 4; i++) {
                sAh[row * SMS + lcol + i] = __uint_as_float(f2tf32(av[i]));
                sBh[row * SMS + lcol + i] = __uint_as_float(f2tf32(bv[i]));
            }
        }
        __syncthreads();

        if (k0 + 32 < K) {
#pragma unroll
            for (int p = 0; p < 4; p++) {
                int row = p * 32 + lrow;
                pva[p] = avalid[p] ? *(const float4*)(A + (size_t)(bm + row) * lda + k0 + 32 + lcol)
                                   : make_float4(0.f, 0.f, 0.f, 0.f);
                pvb[p] = *(const float4*)(Bm + (size_t)(bn + row) * ldb + k0 + 32 + lcol);
            }
        }

#pragma unroll
        for (int ks = 0; ks < 4; ks++) {
            int kb = ks * 8;
            uint32_t ah[4][4], bh[4][2];
#pragma unroll
            for (int mi = 0; mi < 4; mi++) {
                int base = (wm + mi * 16 + gr) * SMS + kb + gc;
                ah[mi][0] = __float_as_uint(sAh[base]);
                ah[mi][1] = __float_as_uint(sAh[base + 8 * SMS]);
                ah[mi][2] = __float_as_uint(sAh[base + 4]);
                ah[mi][3] = __float_as_uint(sAh[base + 8 * SMS + 4]);
            }
#pragma unroll
            for (int ni = 0; ni < 4; ni++) {
                int base = (wn + ni * 8 + gr) * SMS + kb + gc;
                bh[ni][0] = __float_as_uint(sBh[base]);
                bh[ni][1] = __float_as_uint(sBh[base + 4]);
            }
#pragma unroll
            for (int mi = 0; mi < 4; mi++)
#pragma unroll
                for (int ni = 0; ni < 4; ni++)
                    MMA_TF32(acc[mi][ni], ah[mi], bh[ni]);
        }
        __syncthreads();
    }

    // Epilogue
#pragma unroll
    for (int mi = 0; mi < 4; mi++) {
#pragma unroll
        for (int ni = 0; ni < 4; ni++) {
            int col = bn + wn + ni * 8 + gc * 2;
            float b0 = bias ? bias[col] : 0.f;
            float b1 = bias ? bias[col + 1] : 0.f;
            float v[4];
#pragma unroll
            for (int half_ = 0; half_ < 2; half_++) {
                int r = bm + wm + mi * 16 + gr + half_ * 8;
                float x0 = acc[mi][ni][half_ * 2 + 0] + b0;
                float x1 = acc[mi][ni][half_ * 2 + 1] + b1;
                if (EPI == 0) {
                    if (res && r < M) {
                        x0 += res[(size_t)r * ldres + col];
                        x1 += res[(size_t)r * ldres + col + 1];
                    }
                    if (r < M) {
                        float y0 = relu ? fmaxf(x0, 0.f) : x0;
                        float y1 = relu ? fmaxf(x1, 0.f) : x1;
                        C[(size_t)r * ldc + col]     = y0;
                        C[(size_t)r * ldc + col + 1] = y1;
                    }
                } else if (EPI == 1) {
                    *(__half2*)(gqh + (size_t)r * 1024 + col) = __floats2half2_rn(x0, x1);
                } else {  // EPI == 2
                    __half2 hg = *(const __half2*)(gqh + (size_t)r * 1024 + col);
                    x0 += __half2float(__low2half(hg));
                    x1 += __half2float(__high2half(hg));
                }
                v[half_ * 2 + 0] = x0;
                v[half_ * 2 + 1] = x1;
            }
            if (EPI != 0) {
                float p0 = __shfl_xor_sync(~0u, v[0], 1);
                float p1 = __shfl_xor_sync(~0u, v[1], 1);
                float p2 = __shfl_xor_sync(~0u, v[2], 1);
                float p3 = __shfl_xor_sync(~0u, v[3], 1);
                if (!(gc & 1)) {
                    int u = col >> 2;
#pragma unroll
                    for (int half_ = 0; half_ < 2; half_++) {
                        int r = bm + wm + mi * 16 + gr + half_ * 8;
                        float gi = v[half_ * 2], gf = v[half_ * 2 + 1];
                        float gg = half_ ? p2 : p0;
                        float go = half_ ? p3 : p1;
                        float cp = (EPI == 1) ? 0.f : g_c[(size_t)r * 256 + u];
                        float cn = fast_sig(gf) * cp + fast_sig(gi) * fast_tanh(gg);
                        g_c[(size_t)r * 256 + u] = cn;
                        hout[(size_t)r * 256 + u] =
                            g_X[(size_t)r * 256 + u] + fast_sig(go) * fast_tanh(cn);
                    }
                }
            }
        }
    }
}

// ---------------------------------------------------------------------------
// bf16x3 GEMM for the P table (R8 config: register prefetch, single buffer).
// ---------------------------------------------------------------------------
#define BSMS 20
__device__ __forceinline__ void packbf(float f0, float f1, uint32_t& hi, uint32_t& lo)
{
    __nv_bfloat162 h = __floats2bfloat162_rn(f0, f1);
    float r0 = __bfloat162float(h.x), r1 = __bfloat162float(h.y);
    __nv_bfloat162 l = __floats2bfloat162_rn(f0 - r0, f1 - r1);
    hi = *reinterpret_cast<uint32_t*>(&h);
    lo = *reinterpret_cast<uint32_t*>(&l);
}

__global__ __launch_bounds__(256) void bgemm_kernel(
    const float* __restrict__ A, int lda,
    const float* __restrict__ Bm, int ldb,
    float* __restrict__ C, int ldc,
    int M, int N, int K)
{
    extern __shared__ uint32_t smu[];
    uint32_t* sAh = smu;
    uint32_t* sAl = smu + 128 * BSMS;
    uint32_t* sBh = smu + 2 * 128 * BSMS;
    uint32_t* sBl = smu + 3 * 128 * BSMS;

    const int tid = threadIdx.x;
    const int bm = blockIdx.y * 128;
    const int bn = blockIdx.x * 128;
    const int wid = tid >> 5, lane = tid & 31;
    const int wm = (wid >> 2) * 64, wn = (wid & 3) * 32;
    const int gr = lane >> 2, gc = lane & 3;
    const int lrow = tid >> 3;
    const int kp0 = (tid & 7) * 2;

    float acc[4][4][4];
#pragma unroll
    for (int i = 0; i < 4; i++)
#pragma unroll
        for (int j = 0; j < 4; j++)
#pragma unroll
            for (int k = 0; k < 4; k++) acc[i][j][k] = 0.f;

    float4 pva[4], pvb[4];
    const bool avalid[4] = { bm + 0 * 32 + lrow < M, bm + 1 * 32 + lrow < M,
                             bm + 2 * 32 + lrow < M, bm + 3 * 32 + lrow < M };
#pragma unroll
    for (int p = 0; p < 4; p++) {
        int row = p * 32 + lrow;
        pva[p] = avalid[p] ? *(const float4*)(A + (size_t)(bm + row) * lda + kp0 * 2)
                           : make_float4(0.f, 0.f, 0.f, 0.f);
        pvb[p] = *(const float4*)(Bm + (size_t)(bn + row) * ldb + kp0 * 2);
    }

    for (int k0 = 0; k0 < K; k0 += 32) {
#pragma unroll
        for (int p = 0; p < 4; p++) {
            int row = p * 32 + lrow;
            uint32_t h, l;
            packbf(pva[p].x, pva[p].y, h, l); sAh[row * BSMS + kp0] = h;     sAl[row * BSMS + kp0] = l;
            packbf(pva[p].z, pva[p].w, h, l); sAh[row * BSMS + kp0 + 1] = h; sAl[row * BSMS + kp0 + 1] = l;
            packbf(pvb[p].x, pvb[p].y, h, l); sBh[row * BSMS + kp0] = h;     sBl[row * BSMS + kp0] = l;
            packbf(pvb[p].z, pvb[p].w, h, l); sBh[row * BSMS + kp0 + 1] = h; sBl[row * BSMS + kp0 + 1] = l;
        }
        __syncthreads();

        if (k0 + 32 < K) {
#pragma unroll
            for (int p = 0; p < 4; p++) {
                int row = p * 32 + lrow;
                pva[p] = avalid[p] ? *(const float4*)(A + (size_t)(bm + row) * lda + k0 + 32 + kp0 * 2)
                                   : make_float4(0.f, 0.f, 0.f, 0.f);
                pvb[p] = *(const float4*)(Bm + (size_t)(bn + row) * ldb + k0 + 32 + kp0 * 2);
            }
        }

#pragma unroll
        for (int kb = 0; kb < 2; kb++) {
            uint32_t ah[4][4], al[4][4], bh[4][2], bl[4][2];
#pragma unroll
            for (int mi = 0; mi < 4; mi++) {
                int base = (wm + mi * 16 + gr) * BSMS + kb * 8 + gc;
                ah[mi][0] = sAh[base];
                ah[mi][1] = sAh[base + 8 * BSMS];
                ah[mi][2] = sAh[base + 4];
                ah[mi][3] = sAh[base + 8 * BSMS + 4];
                al[mi][0] = sAl[base];
                al[mi][1] = sAl[base + 8 * BSMS];
                al[mi][2] = sAl[base + 4];
                al[mi][3] = sAl[base + 8 * BSMS + 4];
            }
#pragma unroll
            for (int ni = 0; ni < 4; ni++) {
                int base = (wn + ni * 8 + gr) * BSMS + kb * 8 + gc;
                bh[ni][0] = sBh[base];
                bh[ni][1] = sBh[base + 4];
                bl[ni][0] = sBl[base];
                bl[ni][1] = sBl[base + 4];
            }
#pragma unroll
            for (int mi = 0; mi < 4; mi++)
#pragma unroll
                for (int ni = 0; ni < 4; ni++) {
                    MMA_BF16(acc[mi][ni], ah[mi], bh[ni]);
                    MMA_BF16(acc[mi][ni], ah[mi], bl[ni]);
                    MMA_BF16(acc[mi][ni], al[mi], bh[ni]);
                }
        }
        __syncthreads();
    }

#pragma unroll
    for (int mi = 0; mi < 4; mi++)
#pragma unroll
        for (int ni = 0; ni < 4; ni++) {
            int col = bn + wn + ni * 8 + gc * 2;
#pragma unroll
            for (int half_ = 0; half_ < 2; half_++) {
                int r = bm + wm + mi * 16 + gr + half_ * 8;
                if (r < M) {
                    C[(size_t)r * ldc + col]     = acc[mi][ni][half_ * 2 + 0];
                    C[(size_t)r * ldc + col + 1] = acc[mi][ni][half_ * 2 + 1];
                }
            }
        }
}

// ---------------------------------------------------------------------------
// Merged weight packing: blocks [0,128) Wt, [128,1152) Wih+bsum, [1152,2176) WhhL
// ---------------------------------------------------------------------------
__global__ void pack_all_kernel(const float* __restrict__ W,
                                const float* __restrict__ Wih,
                                const float* __restrict__ bih,
                                const float* __restrict__ bhh,
                                const float* __restrict__ Whh)
{
    int b = blockIdx.x, t = threadIdx.x;
    if (b < 128) {
        int n = (b << 1) | (t >> 7);
        int k = t & 127;
        g_Wt[n * 128 + k] = W[(n & 127) * 256 + ((n >> 7) << 7) + k];
    } else if (b < 1152) {
        int j = b - 128;
        int jm = (j & 3) * 512 + (j >> 2);
        g_Wihp[j * 256 + t] = Wih[jm * 256 + t];
        if (t == 0) g_bsum[j] = bih[jm] + bhh[jm];
    } else {
        int j = b - 1152;
        int jm = (j & 3) * 512 + (j >> 2);
        g_WhhLp[j * 256 + t] = Whh[jm * 512 + t];
    }
}

// whhr[j] = dot(g_sg, Whh[jm, 256:512])  (needs se3's g_sg)
__global__ void prep_whhr_kernel(const float* __restrict__ Whh)
{
    int j = blockIdx.x;
    int jm = (j & 3) * 512 + (j >> 2);
    int t = threadIdx.x;
    float p = g_sg[t] * Whh[jm * 512 + 256 + t];
    __shared__ float red[8];
    for (int o = 16; o > 0; o >>= 1) p += __shfl_xor_sync(~0u, p, o);
    if ((t & 31) == 0) red[t >> 5] = p;
    __syncthreads();
    if (t == 0) {
        float s = 0.f;
        for (int i = 0; i < 8; i++) s += red[i];
        g_whhr[j] = s;
    }
}

// ---------------------------------------------------------------------------
// Neighbor encoder: one block (256 thr, 8 warps) per entity. 8202 entities.
// ---------------------------------------------------------------------------
__global__ __launch_bounds__(256) void neighbor_kernel(
                                const int* __restrict__ query,
                                const int* __restrict__ support,
                                const int* __restrict__ q_l1, const int* __restrict__ q_deg_l,
                                const int* __restrict__ q_r1, const int* __restrict__ q_deg_r,
                                const int* __restrict__ s_l1, const int* __restrict__ s_deg_l,
                                const int* __restrict__ s_r1, const int* __restrict__ s_deg_r,
                                const float* __restrict__ sym,
                                const float* __restrict__ gwb, const float* __restrict__ gb,
                                const float* __restrict__ gate_w,
                                const float* __restrict__ gate_temp)
{
    __shared__ __align__(16) float s_self[128], s_bias[128];
    __shared__ __align__(16) float s_proj[MAXK][128];
    __shared__ int   s_conn[2 * MAXK];
    __shared__ float s_cos[MAXK];
    __shared__ float s_gw[MAXK];
    __shared__ int   s_sel[KNEI];
    __shared__ float s_scal[2];

    int e = blockIdx.x;
    const int* conn; int sid, deg; float* outp;
    if (e < 4096)      { conn = q_l1 + e * 100;                sid = query[e * 2];           deg = q_deg_l[e];      outp = g_qvec + e * 256; }
    else if (e < 8192) { int i = e - 4096; conn = q_r1 + i * 100; sid = query[i * 2 + 1];   deg = q_deg_r[i];      outp = g_qvec + i * 256 + 128; }
    else if (e < 8197) { int i = e - 8192; conn = s_l1 + i * 100; sid = support[i * 2];     deg = s_deg_l[i];      outp = g_svec + i * 256; }
    else               { int i = e - 8197; conn = s_r1 + i * 100; sid = support[i * 2 + 1]; deg = s_deg_r[i];      outp = g_svec + i * 256 + 128; }

    int t = threadIdx.x, lane = t & 31, w = t >> 5;
    if (t < 128) {
        s_self[t] = sym[(size_t)sid * 128 + t];
        s_bias[t] = gwb[t] + gb[t];
    } else if (t - 128 < 2 * MAXK) {
        s_conn[t - 128] = conn[t - 128];
    }
    __syncthreads();

    if (w == 0) {
        float ss = 0.f;
#pragma unroll
        for (int i = 0; i < 4; i++) { float v = s_self[lane + 32 * i]; ss += v * v; }
        for (int o = 16; o > 0; o >>= 1) ss += __shfl_xor_sync(~0u, ss, o);
        if (lane == 0) s_scal[0] = sqrtf(ss + EPS);
    } else if (w == 1) {
        if (lane < MAXK) { int r = s_conn[2 * lane]; s_gw[lane] = gate_w[(r == PADID) ? 0 : r]; }
    } else if (w == 2) {
        if (lane + 32 < MAXK) { int r = s_conn[2 * (lane + 32)]; s_gw[lane + 32] = gate_w[(r == PADID) ? 0 : r]; }
    }
    __syncthreads();
    float nself = s_scal[0];

    const float4* self4 = (const float4*)s_self;
    const float4* bias4 = (const float4*)s_bias;
    float4 sf = self4[lane];
    float4 bf = bias4[lane];

#pragma unroll
    for (int it = 0; it < 7; it++) {
        int n = it * 8 + w;
        if (n < MAXK) {
            int rel = s_conn[2 * n], ent = s_conn[2 * n + 1];
            float4 a = ((const float4*)(g_P + (size_t)rel * 256))[lane];
            float4 bb = ((const float4*)(g_P + (size_t)ent * 256 + 128))[lane];
            float va[4] = {a.x + bb.x + bf.x, a.y + bb.y + bf.y,
                           a.z + bb.z + bf.z, a.w + bb.w + bf.w};
            float sfv[4] = {sf.x, sf.y, sf.z, sf.w};
            float dp = 0.f, nn = 0.f;
            float4 pv;
#pragma unroll
            for (int i = 0; i < 4; i++) {
                float v = va[i];
                v = (v > 0.f) ? v : 0.01f * v;
                if (rel == PADID) v = 0.f;
                (&pv.x)[i] = v;
                dp += sfv[i] * v;
                nn += v * v;
            }
            ((float4*)s_proj[n])[lane] = pv;
            for (int o = 16; o > 0; o >>= 1) {
                dp += __shfl_xor_sync(~0u, dp, o);
                nn += __shfl_xor_sync(~0u, nn, o);
            }
            if (lane == 0) {
                float nnei = sqrtf(nn + EPS);
                s_cos[n] = dp / (nself * nnei + EPS);
            }
        }
    }
    __syncthreads();

    if (w == 0) {
        float v0 = s_cos[lane];
        float v1 = (lane + 32 < MAXK) ? s_cos[lane + 32] : -3.0e38f;
#pragma unroll
        for (int k = 0; k < KNEI; k++) {
            float bv = v0; int bi = lane;
            if (v1 > bv) { bv = v1; bi = lane + 32; }
            for (int o = 16; o > 0; o >>= 1) {
                float ov = __shfl_xor_sync(~0u, bv, o);
                int   oi = __shfl_xor_sync(~0u, bi, o);
                if (ov > bv || (ov == bv && oi < bi)) { bv = ov; bi = oi; }
            }
            if (lane == 0) s_sel[k] = bi;
            if (bi == lane) v0 = -3.0e38f;
            else if (bi == lane + 32) v1 = -3.0e38f;
        }
    } else if (w == 1) {
        float gv = s_gw[lane];
        gv += (lane + 32 < MAXK) ? s_gw[lane + 32] : 0.f;
        for (int o = 16; o > 0; o >>= 1) gv += __shfl_xor_sync(~0u, gv, o);
        if (lane == 0) {
            float gate = fast_sig((gv / 50.f) / gate_temp[0]);
            if (deg <= 0) gate = 1.f;
            s_scal[1] = gate;
        }
    }
    __syncthreads();

    if (t < 128) {
        float agg = 0.f;
#pragma unroll
        for (int k = 0; k < KNEI; k++) agg += s_proj[s_sel[k]][t];
        agg /= 10.f;
        outp[t] = fast_tanh(s_self[t] + s_scal[1] * agg);
    }
}

// ---------------------------------------------------------------------------
// Support encoder stages
// ---------------------------------------------------------------------------
__global__ void se1_kernel(const float* __restrict__ W1, const float* __restrict__ b1)
{
    int gw = (blockIdx.x * blockDim.x + threadIdx.x) >> 5;
    int lane = threadIdx.x & 31;
    if (gw >= FEW * 512) return;
    int r = gw >> 9, j = gw & 511;
    const float4* x = (const float4*)(g_svec + r * 256);
    const float4* w = (const float4*)(W1 + (size_t)j * 256);
    float acc = 0.f;
#pragma unroll
    for (int k = lane; k < 64; k += 32) {
        float4 xv = x[k], wv = w[k];
        acc = fmaf(xv.x, wv.x, acc); acc = fmaf(xv.y, wv.y, acc);
        acc = fmaf(xv.z, wv.z, acc); acc = fmaf(xv.w, wv.w, acc);
    }
    for (int o = 16; o > 0; o >>= 1) acc += __shfl_xor_sync(~0u, acc, o);
    if (lane == 0) g_sh1[r * 512 + j] = fmaxf(acc + b1[j], 0.f);
}

__global__ void se2_kernel(const float* __restrict__ W2, const float* __restrict__ b2)
{
    int gw = (blockIdx.x * blockDim.x + threadIdx.x) >> 5;
    int lane = threadIdx.x & 31;
    if (gw >= FEW * 256) return;
    int r = gw >> 8, c = gw & 255;
    const float4* x = (const float4*)(g_sh1 + r * 512);
    const float4* w = (const float4*)(W2 + (size_t)c * 512);
    float acc = 0.f;
#pragma unroll
    for (int k = lane; k < 128; k += 32) {
        float4 xv = x[k], wv = w[k];
        acc = fmaf(xv.x, wv.x, acc); acc = fmaf(xv.y, wv.y, acc);
        acc = fmaf(xv.z, wv.z, acc); acc = fmaf(xv.w, wv.w, acc);
    }
    for (int o = 16; o > 0; o >>= 1) acc += __shfl_xor_sync(~0u, acc, o);
    if (lane == 0) g_sh[r * 256 + c] = acc + b2[c] + g_svec[r * 256 + c];
}

__global__ void se3_kernel(const float* __restrict__ g, const float* __restrict__ b)
{
    __shared__ float smu[FEW], srs[FEW];
    __shared__ float red[8];
    int t = threadIdx.x, lane = t & 31, w = t >> 5;

    if (w < FEW) {
        const float* row = g_sh + w * 256;
        float s = 0.f;
#pragma unroll
        for (int i = 0; i < 8; i++) s += row[lane + 32 * i];
        for (int o = 16; o > 0; o >>= 1) s += __shfl_xor_sync(~0u, s, o);
        float mu = s / 256.f;
        float q = 0.f;
#pragma unroll
        for (int i = 0; i < 8; i++) { float d = row[lane + 32 * i] - mu; q += d * d; }
        for (int o = 16; o > 0; o >>= 1) q += __shfl_xor_sync(~0u, q, o);
        if (lane == 0) { smu[w] = mu; srs[w] = 1.f / sqrtf(q / 256.f + LNEPS); }
    }
    __syncthreads();

    float acc = 0.f;
#pragma unroll
    for (int r = 0; r < FEW; r++)
        acc += g[t] * (g_sh[r * 256 + t] - smu[r]) * srs[r] + b[t];
    acc *= 0.2f;
    g_sg[t] = acc;

    float nq = acc * acc;
    for (int o = 16; o > 0; o >>= 1) nq += __shfl_xor_sync(~0u, nq, o);
    if (lane == 0) red[w] = nq;
    __syncthreads();
    if (t == 0) {
        float s = 0.f;
        for (int i = 0; i < 8; i++) s += red[i];
        g_sgn[0] = sqrtf(s + EPS);
    }
}

// ---------------------------------------------------------------------------
// LayerNorm rows of g_tmp -> g_X
// ---------------------------------------------------------------------------
__global__ void ln_kernel(const float* __restrict__ g, const float* __restrict__ b)
{
    int row = blockIdx.x, t = threadIdx.x;
    float v = g_tmp[(size_t)row * 256 + t];
    __shared__ float red[8];
    __shared__ float s_mu, s_rs;
    float s = v;
    for (int o = 16; o > 0; o >>= 1) s += __shfl_xor_sync(~0u, s, o);
    if ((t & 31) == 0) red[t >> 5] = s;
    __syncthreads();
    if (t == 0) { float m = 0.f; for (int i = 0; i < 8; i++) m += red[i]; s_mu = m / 256.f; }
    __syncthreads();
    float d = v - s_mu;
    float q = d * d;
    for (int o = 16; o > 0; o >>= 1) q += __shfl_xor_sync(~0u, q, o);
    if ((t & 31) == 0) red[t >> 5] = q;
    __syncthreads();
    if (t == 0) { float m = 0.f; for (int i = 0; i < 8; i++) m += red[i]; s_rs = 1.f / sqrtf(m / 256.f + LNEPS); }
    __syncthreads();
    g_X[(size_t)row * 256 + t] = g[t] * d * s_rs + b[t];
}

// ---------------------------------------------------------------------------
// Final cosine vs support_g
// ---------------------------------------------------------------------------
__global__ void final_kernel(const float* __restrict__ h_in, float* __restrict__ out)
{
    __shared__ float ssg[256];
    int t = threadIdx.x, lane = t & 31, w = t >> 5;
    ssg[t] = g_sg[t];
    __syncthreads();
    int row = blockIdx.x * 8 + w;
    const float* h = h_in + (size_t)row * 256;
    float dp = 0.f, nq = 0.f;
#pragma unroll
    for (int i = 0; i < 8; i++) {
        int d = lane + 32 * i;
        float v = h[d];
        dp += v * ssg[d];
        nq += v * v;
    }
    for (int o = 16; o > 0; o >>= 1) {
        dp += __shfl_xor_sync(~0u, dp, o);
        nq += __shfl_xor_sync(~0u, nq, o);
    }
    if (lane == 0) out[row] = dp / (sqrtf(nq + EPS) * g_sgn[0]);
}

// ---------------------------------------------------------------------------
// kernel_launch (single stream)
// ---------------------------------------------------------------------------
extern "C" void kernel_launch(void* const* d_in, const int* in_sizes, int n_in,
                              void* d_out, int out_size)
{
    const int*   query     = (const int*)d_in[0];
    const int*   support   = (const int*)d_in[1];
    const int*   q_l1      = (const int*)d_in[2];
    const int*   q_deg_l   = (const int*)d_in[3];
    const int*   q_r1      = (const int*)d_in[4];
    const int*   q_deg_r   = (const int*)d_in[5];
    const int*   s_l1      = (const int*)d_in[6];
    const int*   s_deg_l   = (const int*)d_in[7];
    const int*   s_r1      = (const int*)d_in[8];
    const int*   s_deg_r   = (const int*)d_in[9];
    const float* sym       = (const float*)d_in[10];
    const float* gcn_w_W   = (const float*)d_in[11];
    const float* gcn_w_b   = (const float*)d_in[12];
    const float* gcn_b     = (const float*)d_in[13];
    const float* gate_w    = (const float*)d_in[14];
    const float* gate_temp = (const float*)d_in[15];
    const float* se_W1     = (const float*)d_in[16];
    const float* se_b1     = (const float*)d_in[17];
    const float* se_W2     = (const float*)d_in[18];
    const float* se_b2     = (const float*)d_in[19];
    const float* ln_g      = (const float*)d_in[20];
    const float* ln_b      = (const float*)d_in[21];
    const float* lstm_Wih  = (const float*)d_in[22];
    const float* lstm_Whh  = (const float*)d_in[23];
    const float* lstm_bih  = (const float*)d_in[24];
    const float* lstm_bhh  = (const float*)d_in[25];
    float* out = (float*)d_out;

    float *pP, *pQv, *pH1, *pTmp, *pX, *pWihp, *pWhhLp, *pBsum, *pWhhr, *pH, *pH2, *pWt;
    __half* pGq;
    cudaGetSymbolAddress((void**)&pP,     g_P);
    cudaGetSymbolAddress((void**)&pWt,    g_Wt);
    cudaGetSymbolAddress((void**)&pQv,    g_qvec);
    cudaGetSymbolAddress((void**)&pH1,    g_H1);
    cudaGetSymbolAddress((void**)&pTmp,   g_tmp);
    cudaGetSymbolAddress((void**)&pX,     g_X);
    cudaGetSymbolAddress((void**)&pWihp,  g_Wihp);
    cudaGetSymbolAddress((void**)&pWhhLp, g_WhhLp);
    cudaGetSymbolAddress((void**)&pBsum,  g_bsum);
    cudaGetSymbolAddress((void**)&pWhhr,  g_whhr);
    cudaGetSymbolAddress((void**)&pGq,    g_Gq);
    cudaGetSymbolAddress((void**)&pH,     g_h);
    cudaGetSymbolAddress((void**)&pH2,    g_h2);

    const int SM_T = 2 * 128 * SMS * (int)sizeof(float);     // 36864
    const int SM_B = 4 * 128 * BSMS * (int)sizeof(uint32_t); // 40960
    static int attr_done = 0;
    if (!attr_done) {
        cudaFuncSetAttribute(tgemm_kernel<0>, cudaFuncAttributeMaxDynamicSharedMemorySize, SM_T);
        cudaFuncSetAttribute(tgemm_kernel<1>, cudaFuncAttributeMaxDynamicSharedMemorySize, SM_T);
        cudaFuncSetAttribute(tgemm_kernel<2>, cudaFuncAttributeMaxDynamicSharedMemorySize, SM_T);
        cudaFuncSetAttribute(bgemm_kernel,    cudaFuncAttributeMaxDynamicSharedMemorySize, SM_B);
        attr_done = 1;
    }

    // 1) merged weight packing
    pack_all_kernel<<<2176, 256>>>(gcn_w_W, lstm_Wih, lstm_bih, lstm_bhh, lstm_Whh);

    // 2) P = sym_emb @ Wt^T  (bf16x3)
    bgemm_kernel<<<dim3(2, (NSYM + 1 + 127) / 128), 256, SM_B>>>(
        sym, 128, pWt, 128, pP, 256, NSYM + 1, 256, 128);

    // 3) neighbor encoder -> g_qvec, g_svec
    neighbor_kernel<<<8202, 256>>>(query, support, q_l1, q_deg_l, q_r1, q_deg_r,
                                   s_l1, s_deg_l, s_r1, s_deg_r,
                                   sym, gcn_w_b, gcn_b, gate_w, gate_temp);

    // 4) query SE GEMM 1   <- ncu window
    tgemm_kernel<0><<<dim3(4, 32), 256, SM_T>>>(pQv, 256, se_W1, 256, pH1, 512,
                                                B, 512, 256, se_b1, nullptr, 0, 1, nullptr, nullptr);

    // 5-8) support encoder + whhr
    se1_kernel<<<(FEW * 512 + 7) / 8, 256>>>(se_W1, se_b1);
    se2_kernel<<<(FEW * 256 + 7) / 8, 256>>>(se_W2, se_b2);
    se3_kernel<<<1, 256>>>(ln_g, ln_b);
    prep_whhr_kernel<<<1024, 256>>>(lstm_Whh);

    // 9-10) query SE GEMM 2 + LN
    tgemm_kernel<0><<<dim3(2, 32), 256, SM_T>>>(pH1, 512, se_W2, 512, pTmp, 256,
                                                B, 256, 512, se_b2, pQv, 256, 0, nullptr, nullptr);
    ln_kernel<<<B, 256>>>(ln_g, ln_b);

    // 11) Gq = X @ Wihp^T + bsum (fp16 store); fused LSTM step 1 -> h in g_h
    tgemm_kernel<1><<<dim3(8, 32), 256, SM_T>>>(pX, 256, pWihp, 256, nullptr, 0,
                                                B, 1024, 256, pBsum, nullptr, 0, 0, pH, pGq);

    // 12-14) LSTM steps 2..4 (fused elementwise, fp16 Gq residual, double-buffered h)
    tgemm_kernel<2><<<dim3(8, 32), 256, SM_T>>>(pH, 256, pWhhLp, 256, nullptr, 0,
                                                B, 1024, 256, pWhhr, nullptr, 0, 0, pH2, pGq);
    tgemm_kernel<2><<<dim3(8, 32), 256, SM_T>>>(pH2, 256, pWhhLp, 256, nullptr, 0,
                                                B, 1024, 256, pWhhr, nullptr, 0, 0, pH, pGq);
    tgemm_kernel<2><<<dim3(8, 32), 256, SM_T>>>(pH, 256, pWhhLp, 256, nullptr, 0,
                                                B, 1024, 256, pWhhr, nullptr, 0, 0, pH2, pGq);

    // 15) final cosine
    final_kernel<<<B / 8, 256>>>(pH2, out);
}

// round 14
// speedup vs baseline: 1.0553x; 1.0398x over previous
#include <cuda_runtime.h>
#include <cuda_bf16.h>
#include <cuda_fp16.h>
#include <math.h>
#include <stdint.h>

#define NSYM   100000
#define PADID  100000
#define B      4096
#define FEW    5
#define MAXK   50
#define KNEI   10
#define EPS    1e-8f
#define LNEPS  1e-5f

// ---------------------------------------------------------------------------
// Scratch (device globals -- no allocations allowed)
// ---------------------------------------------------------------------------
__device__ __align__(128) float g_P[(NSYM + 1) * 256];
__device__ __align__(128) float g_Wt[256 * 128];
__device__ __align__(128) float g_qvec[B * 256];
__device__ __align__(128) float g_svec[FEW * 256];
__device__ __align__(128) float g_sh1[FEW * 512];
__device__ __align__(128) float g_sh[FEW * 256];
__device__ __align__(128) float g_sg[256];
__device__ __align__(128) float g_sgn[1];
__device__ __align__(128) float g_H1[B * 512];
__device__ __align__(128) float g_tmp[B * 256];
__device__ __align__(128) float g_X[B * 256];
__device__ __align__(128) float g_Wihp[1024 * 256];
__device__ __align__(128) float g_WhhLp[1024 * 256];
__device__ __align__(128) float g_bsum[1024];
__device__ __align__(128) float g_whhr[1024];
__device__ __align__(128) __half g_Gq[B * 1024];
__device__ __align__(128) float g_c[B * 256];
__device__ __align__(128) float g_h[B * 256];
__device__ __align__(128) float g_h2[B * 256];

__device__ __forceinline__ float fast_tanh(float x) {
    float y;
    asm("tanh.approx.f32 %0, %1;" : "=f"(y) : "f"(x));
    return y;
}
__device__ __forceinline__ float fast_sig(float x) {
    return 0.5f * fast_tanh(0.5f * x) + 0.5f;
}

#define MMA_TF32(d, a, b)                                                     \
    asm volatile("mma.sync.aligned.m16n8k8.row.col.f32.tf32.tf32.f32 "        \
                 "{%0,%1,%2,%3}, {%4,%5,%6,%7}, {%8,%9}, {%0,%1,%2,%3};"      \
                 : "+f"(d[0]), "+f"(d[1]), "+f"(d[2]), "+f"(d[3])             \
                 : "r"(a[0]), "r"(a[1]), "r"(a[2]), "r"(a[3]),                \
                   "r"(b[0]), "r"(b[1]))

#define MMA_BF16(d, a, b)                                                     \
    asm volatile("mma.sync.aligned.m16n8k16.row.col.f32.bf16.bf16.f32 "       \
                 "{%0,%1,%2,%3}, {%4,%5,%6,%7}, {%8,%9}, {%0,%1,%2,%3};"      \
                 : "+f"(d[0]), "+f"(d[1]), "+f"(d[2]), "+f"(d[3])             \
                 : "r"(a[0]), "r"(a[1]), "r"(a[2]), "r"(a[3]),                \
                   "r"(b[0]), "r"(b[1]))

#define CP_ASYNC16(dst, src)                                                  \
    asm volatile("cp.async.ca.shared.global [%0], [%1], 16;"                  \
                 :: "r"(dst), "l"(src))
#define CP_ASYNC16Z(dst, src, sz)                                             \
    asm volatile("cp.async.ca.shared.global [%0], [%1], 16, %2;"              \
                 :: "r"(dst), "l"(src), "r"(sz))
#define CP_COMMIT()  asm volatile("cp.async.commit_group;")
#define CP_WAIT1()   asm volatile("cp.async.wait_group 1;")
#define CP_WAIT0()   asm volatile("cp.async.wait_group 0;")

// ---------------------------------------------------------------------------
// TF32 tensor-core GEMM, cp.async double-buffered smem pipeline.
// Raw fp32 tiles in smem act as truncated tf32 operands (HW ignores low bits).
// C[M,N] = A[M,K] @ B[N,K]^T (+bias[n]) (+res) (relu?)
// BM=BN=128, BK=32, 256 threads (8 warps, 2x4), warp tile 64x32.
// EPI=0: generic. EPI=1: LSTM step 1 (fp16 gate store). EPI=2: LSTM steps 2-4.
// ---------------------------------------------------------------------------
#define SMS 36
#define TBUFS (2 * 128 * SMS)   // floats per buffer (A plane + B plane)
template <int EPI>
__global__ __launch_bounds__(256) void tgemm_kernel(
    const float* __restrict__ A, int lda,
    const float* __restrict__ Bm, int ldb,
    float* __restrict__ C, int ldc,
    int M, int N, int K,
    const float* __restrict__ bias,
    const float* __restrict__ res, int ldres,
    int relu,
    float* __restrict__ hout,
    __half* __restrict__ gqh)
{
    extern __shared__ float sm[];

    const int tid = threadIdx.x;
    const int bm = blockIdx.y * 128;
    const int bn = blockIdx.x * 128;
    const int wid = tid >> 5, lane = tid & 31;
    const int wm = (wid >> 2) * 64, wn = (wid & 3) * 32;
    const int gr = lane >> 2, gc = lane & 3;
    const int lrow = tid >> 3;
    const int lcol = (tid & 7) * 4;

    float acc[4][4][4];
#pragma unroll
    for (int i = 0; i < 4; i++)
#pragma unroll
        for (int j = 0; j < 4; j++)
#pragma unroll
            for (int k = 0; k < 4; k++) acc[i][j][k] = 0.f;

    const float* asrc[4];
    const float* bsrc[4];
    int asz[4];
#pragma unroll
    for (int p = 0; p < 4; p++) {
        int row = p * 32 + lrow;
        asrc[p] = A + (size_t)(bm + row) * lda + lcol;
        bsrc[p] = Bm + (size_t)(bn + row) * ldb + lcol;
        asz[p] = (bm + row < M) ? 16 : 0;
    }
    uint32_t sbaseA[2], sbaseB[2];
#pragma unroll
    for (int b_ = 0; b_ < 2; b_++) {
        sbaseA[b_] = (uint32_t)__cvta_generic_to_shared(sm + b_ * TBUFS + lrow * SMS + lcol);
        sbaseB[b_] = (uint32_t)__cvta_generic_to_shared(sm + b_ * TBUFS + 128 * SMS + lrow * SMS + lcol);
    }
    const uint32_t rowstep = 32 * SMS * 4;   // bytes for 32 smem rows

    // issue tile 0 -> buffer 0
#pragma unroll
    for (int p = 0; p < 4; p++) {
        CP_ASYNC16Z(sbaseA[0] + p * rowstep, asrc[p], asz[p]);
        CP_ASYNC16(sbaseB[0] + p * rowstep, bsrc[p]);
    }
    CP_COMMIT();

    const int KT = K >> 5;
    for (int kt = 0; kt < KT; kt++) {
        if (kt + 1 < KT) {
            int buf = (kt + 1) & 1;
            int off = (kt + 1) * 32;
#pragma unroll
            for (int p = 0; p < 4; p++) {
                CP_ASYNC16Z(sbaseA[buf] + p * rowstep, asrc[p] + off, asz[p]);
                CP_ASYNC16(sbaseB[buf] + p * rowstep, bsrc[p] + off);
            }
            CP_COMMIT();
            CP_WAIT1();
        } else {
            CP_WAIT0();
        }
        __syncthreads();

        const float* sAh = sm + (kt & 1) * TBUFS;
        const float* sBh = sAh + 128 * SMS;
#pragma unroll
        for (int ks = 0; ks < 4; ks++) {
            int kb = ks * 8;
            uint32_t ah[4][4], bh[4][2];
#pragma unroll
            for (int mi = 0; mi < 4; mi++) {
                int base = (wm + mi * 16 + gr) * SMS + kb + gc;
                ah[mi][0] = __float_as_uint(sAh[base]);
                ah[mi][1] = __float_as_uint(sAh[base + 8 * SMS]);
                ah[mi][2] = __float_as_uint(sAh[base + 4]);
                ah[mi][3] = __float_as_uint(sAh[base + 8 * SMS + 4]);
            }
#pragma unroll
            for (int ni = 0; ni < 4; ni++) {
                int base = (wn + ni * 8 + gr) * SMS + kb + gc;
                bh[ni][0] = __float_as_uint(sBh[base]);
                bh[ni][1] = __float_as_uint(sBh[base + 4]);
            }
#pragma unroll
            for (int mi = 0; mi < 4; mi++)
#pragma unroll
                for (int ni = 0; ni < 4; ni++)
                    MMA_TF32(acc[mi][ni], ah[mi], bh[ni]);
        }
        __syncthreads();   // protect buffer before overwrite two tiles later
    }

    // Epilogue
#pragma unroll
    for (int mi = 0; mi < 4; mi++) {
#pragma unroll
        for (int ni = 0; ni < 4; ni++) {
            int col = bn + wn + ni * 8 + gc * 2;
            float b0 = bias ? bias[col] : 0.f;
            float b1 = bias ? bias[col + 1] : 0.f;
            float v[4];
#pragma unroll
            for (int half_ = 0; half_ < 2; half_++) {
                int r = bm + wm + mi * 16 + gr + half_ * 8;
                float x0 = acc[mi][ni][half_ * 2 + 0] + b0;
                float x1 = acc[mi][ni][half_ * 2 + 1] + b1;
                if (EPI == 0) {
                    if (res && r < M) {
                        x0 += res[(size_t)r * ldres + col];
                        x1 += res[(size_t)r * ldres + col + 1];
                    }
                    if (r < M) {
                        float y0 = relu ? fmaxf(x0, 0.f) : x0;
                        float y1 = relu ? fmaxf(x1, 0.f) : x1;
                        C[(size_t)r * ldc + col]     = y0;
                        C[(size_t)r * ldc + col + 1] = y1;
                    }
                } else if (EPI == 1) {
                    *(__half2*)(gqh + (size_t)r * 1024 + col) = __floats2half2_rn(x0, x1);
                } else {  // EPI == 2
                    __half2 hg = *(const __half2*)(gqh + (size_t)r * 1024 + col);
                    x0 += __half2float(__low2half(hg));
                    x1 += __half2float(__high2half(hg));
                }
                v[half_ * 2 + 0] = x0;
                v[half_ * 2 + 1] = x1;
            }
            if (EPI != 0) {
                float p0 = __shfl_xor_sync(~0u, v[0], 1);
                float p1 = __shfl_xor_sync(~0u, v[1], 1);
                float p2 = __shfl_xor_sync(~0u, v[2], 1);
                float p3 = __shfl_xor_sync(~0u, v[3], 1);
                if (!(gc & 1)) {
                    int u = col >> 2;
#pragma unroll
                    for (int half_ = 0; half_ < 2; half_++) {
                        int r = bm + wm + mi * 16 + gr + half_ * 8;
                        float gi = v[half_ * 2], gf = v[half_ * 2 + 1];
                        float gg = half_ ? p2 : p0;
                        float go = half_ ? p3 : p1;
                        float cp = (EPI == 1) ? 0.f : g_c[(size_t)r * 256 + u];
                        float cn = fast_sig(gf) * cp + fast_sig(gi) * fast_tanh(gg);
                        g_c[(size_t)r * 256 + u] = cn;
                        hout[(size_t)r * 256 + u] =
                            g_X[(size_t)r * 256 + u] + fast_sig(go) * fast_tanh(cn);
                    }
                }
            }
        }
    }
}

// ---------------------------------------------------------------------------
// bf16x3 GEMM for the P table (R8 config: register prefetch, single buffer).
// ---------------------------------------------------------------------------
#define BSMS 20
__device__ __forceinline__ void packbf(float f0, float f1, uint32_t& hi, uint32_t& lo)
{
    __nv_bfloat162 h = __floats2bfloat162_rn(f0, f1);
    float r0 = __bfloat162float(h.x), r1 = __bfloat162float(h.y);
    __nv_bfloat162 l = __floats2bfloat162_rn(f0 - r0, f1 - r1);
    hi = *reinterpret_cast<uint32_t*>(&h);
    lo = *reinterpret_cast<uint32_t*>(&l);
}

__global__ __launch_bounds__(256) void bgemm_kernel(
    const float* __restrict__ A, int lda,
    const float* __restrict__ Bm, int ldb,
    float* __restrict__ C, int ldc,
    int M, int N, int K)
{
    extern __shared__ uint32_t smu[];
    uint32_t* sAh = smu;
    uint32_t* sAl = smu + 128 * BSMS;
    uint32_t* sBh = smu + 2 * 128 * BSMS;
    uint32_t* sBl = smu + 3 * 128 * BSMS;

    const int tid = threadIdx.x;
    const int bm = blockIdx.y * 128;
    const int bn = blockIdx.x * 128;
    const int wid = tid >> 5, lane = tid & 31;
    const int wm = (wid >> 2) * 64, wn = (wid & 3) * 32;
    const int gr = lane >> 2, gc = lane & 3;
    const int lrow = tid >> 3;
    const int kp0 = (tid & 7) * 2;

    float acc[4][4][4];
#pragma unroll
    for (int i = 0; i < 4; i++)
#pragma unroll
        for (int j = 0; j < 4; j++)
#pragma unroll
            for (int k = 0; k < 4; k++) acc[i][j][k] = 0.f;

    float4 pva[4], pvb[4];
    const bool avalid[4] = { bm + 0 * 32 + lrow < M, bm + 1 * 32 + lrow < M,
                             bm + 2 * 32 + lrow < M, bm + 3 * 32 + lrow < M };
#pragma unroll
    for (int p = 0; p < 4; p++) {
        int row = p * 32 + lrow;
        pva[p] = avalid[p] ? *(const float4*)(A + (size_t)(bm + row) * lda + kp0 * 2)
                           : make_float4(0.f, 0.f, 0.f, 0.f);
        pvb[p] = *(const float4*)(Bm + (size_t)(bn + row) * ldb + kp0 * 2);
    }

    for (int k0 = 0; k0 < K; k0 += 32) {
#pragma unroll
        for (int p = 0; p < 4; p++) {
            int row = p * 32 + lrow;
            uint32_t h, l;
            packbf(pva[p].x, pva[p].y, h, l); sAh[row * BSMS + kp0] = h;     sAl[row * BSMS + kp0] = l;
            packbf(pva[p].z, pva[p].w, h, l); sAh[row * BSMS + kp0 + 1] = h; sAl[row * BSMS + kp0 + 1] = l;
            packbf(pvb[p].x, pvb[p].y, h, l); sBh[row * BSMS + kp0] = h;     sBl[row * BSMS + kp0] = l;
            packbf(pvb[p].z, pvb[p].w, h, l); sBh[row * BSMS + kp0 + 1] = h; sBl[row * BSMS + kp0 + 1] = l;
        }
        __syncthreads();

        if (k0 + 32 < K) {
#pragma unroll
            for (int p = 0; p < 4; p++) {
                int row = p * 32 + lrow;
                pva[p] = avalid[p] ? *(const float4*)(A + (size_t)(bm + row) * lda + k0 + 32 + kp0 * 2)
                                   : make_float4(0.f, 0.f, 0.f, 0.f);
                pvb[p] = *(const float4*)(Bm + (size_t)(bn + row) * ldb + k0 + 32 + kp0 * 2);
            }
        }

#pragma unroll
        for (int kb = 0; kb < 2; kb++) {
            uint32_t ah[4][4], al[4][4], bh[4][2], bl[4][2];
#pragma unroll
            for (int mi = 0; mi < 4; mi++) {
                int base = (wm + mi * 16 + gr) * BSMS + kb * 8 + gc;
                ah[mi][0] = sAh[base];
                ah[mi][1] = sAh[base + 8 * BSMS];
                ah[mi][2] = sAh[base + 4];
                ah[mi][3] = sAh[base + 8 * BSMS + 4];
                al[mi][0] = sAl[base];
                al[mi][1] = sAl[base + 8 * BSMS];
                al[mi][2] = sAl[base + 4];
                al[mi][3] = sAl[base + 8 * BSMS + 4];
            }
#pragma unroll
            for (int ni = 0; ni < 4; ni++) {
                int base = (wn + ni * 8 + gr) * BSMS + kb * 8 + gc;
                bh[ni][0] = sBh[base];
                bh[ni][1] = sBh[base + 4];
                bl[ni][0] = sBl[base];
                bl[ni][1] = sBl[base + 4];
            }
#pragma unroll
            for (int mi = 0; mi < 4; mi++)
#pragma unroll
                for (int ni = 0; ni < 4; ni++) {
                    MMA_BF16(acc[mi][ni], ah[mi], bh[ni]);
                    MMA_BF16(acc[mi][ni], ah[mi], bl[ni]);
                    MMA_BF16(acc[mi][ni], al[mi], bh[ni]);
                }
        }
        __syncthreads();
    }

#pragma unroll
    for (int mi = 0; mi < 4; mi++)
#pragma unroll
        for (int ni = 0; ni < 4; ni++) {
            int col = bn + wn + ni * 8 + gc * 2;
#pragma unroll
            for (int half_ = 0; half_ < 2; half_++) {
                int r = bm + wm + mi * 16 + gr + half_ * 8;
                if (r < M) {
                    C[(size_t)r * ldc + col]     = acc[mi][ni][half_ * 2 + 0];
                    C[(size_t)r * ldc + col + 1] = acc[mi][ni][half_ * 2 + 1];
                }
            }
        }
}

// ---------------------------------------------------------------------------
// Merged weight packing: blocks [0,128) Wt, [128,1152) Wih+bsum, [1152,2176) WhhL
// ---------------------------------------------------------------------------
__global__ void pack_all_kernel(const float* __restrict__ W,
                                const float* __restrict__ Wih,
                                const float* __restrict__ bih,
                                const float* __restrict__ bhh,
                                const float* __restrict__ Whh)
{
    int b = blockIdx.x, t = threadIdx.x;
    if (b < 128) {
        int n = (b << 1) | (t >> 7);
        int k = t & 127;
        g_Wt[n * 128 + k] = W[(n & 127) * 256 + ((n >> 7) << 7) + k];
    } else if (b < 1152) {
        int j = b - 128;
        int jm = (j & 3) * 512 + (j >> 2);
        g_Wihp[j * 256 + t] = Wih[jm * 256 + t];
        if (t == 0) g_bsum[j] = bih[jm] + bhh[jm];
    } else {
        int j = b - 1152;
        int jm = (j & 3) * 512 + (j >> 2);
        g_WhhLp[j * 256 + t] = Whh[jm * 512 + t];
    }
}

// whhr[j] = dot(g_sg, Whh[jm, 256:512])
__global__ void prep_whhr_kernel(const float* __restrict__ Whh)
{
    int j = blockIdx.x;
    int jm = (j & 3) * 512 + (j >> 2);
    int t = threadIdx.x;
    float p = g_sg[t] * Whh[jm * 512 + 256 + t];
    __shared__ float red[8];
    for (int o = 16; o > 0; o >>= 1) p += __shfl_xor_sync(~0u, p, o);
    if ((t & 31) == 0) red[t >> 5] = p;
    __syncthreads();
    if (t == 0) {
        float s = 0.f;
        for (int i = 0; i < 8; i++) s += red[i];
        g_whhr[j] = s;
    }
}

// ---------------------------------------------------------------------------
// Neighbor encoder: one block (256 thr, 8 warps) per entity. 8202 entities.
// ---------------------------------------------------------------------------
__global__ __launch_bounds__(256) void neighbor_kernel(
                                const int* __restrict__ query,
                                const int* __restrict__ support,
                                const int* __restrict__ q_l1, const int* __restrict__ q_deg_l,
                                const int* __restrict__ q_r1, const int* __restrict__ q_deg_r,
                                const int* __restrict__ s_l1, const int* __restrict__ s_deg_l,
                                const int* __restrict__ s_r1, const int* __restrict__ s_deg_r,
                                const float* __restrict__ sym,
                                const float* __restrict__ gwb, const float* __restrict__ gb,
                                const float* __restrict__ gate_w,
                                const float* __restrict__ gate_temp)
{
    __shared__ __align__(16) float s_self[128], s_bias[128];
    __shared__ __align__(16) float s_proj[MAXK][128];
    __shared__ int   s_conn[2 * MAXK];
    __shared__ float s_cos[MAXK];
    __shared__ float s_gw[MAXK];
    __shared__ int   s_sel[KNEI];
    __shared__ float s_scal[2];

    int e = blockIdx.x;
    const int* conn; int sid, deg; float* outp;
    if (e < 4096)      { conn = q_l1 + e * 100;                sid = query[e * 2];           deg = q_deg_l[e];      outp = g_qvec + e * 256; }
    else if (e < 8192) { int i = e - 4096; conn = q_r1 + i * 100; sid = query[i * 2 + 1];   deg = q_deg_r[i];      outp = g_qvec + i * 256 + 128; }
    else if (e < 8197) { int i = e - 8192; conn = s_l1 + i * 100; sid = support[i * 2];     deg = s_deg_l[i];      outp = g_svec + i * 256; }
    else               { int i = e - 8197; conn = s_r1 + i * 100; sid = support[i * 2 + 1]; deg = s_deg_r[i];      outp = g_svec + i * 256 + 128; }

    int t = threadIdx.x, lane = t & 31, w = t >> 5;
    if (t < 128) {
        s_self[t] = sym[(size_t)sid * 128 + t];
        s_bias[t] = gwb[t] + gb[t];
    } else if (t - 128 < 2 * MAXK) {
        s_conn[t - 128] = conn[t - 128];
    }
    __syncthreads();

    if (w == 0) {
        float ss = 0.f;
#pragma unroll
        for (int i = 0; i < 4; i++) { float v = s_self[lane + 32 * i]; ss += v * v; }
        for (int o = 16; o > 0; o >>= 1) ss += __shfl_xor_sync(~0u, ss, o);
        if (lane == 0) s_scal[0] = sqrtf(ss + EPS);
    } else if (w == 1) {
        if (lane < MAXK) { int r = s_conn[2 * lane]; s_gw[lane] = gate_w[(r == PADID) ? 0 : r]; }
    } else if (w == 2) {
        if (lane + 32 < MAXK) { int r = s_conn[2 * (lane + 32)]; s_gw[lane + 32] = gate_w[(r == PADID) ? 0 : r]; }
    }
    __syncthreads();
    float nself = s_scal[0];

    const float4* self4 = (const float4*)s_self;
    const float4* bias4 = (const float4*)s_bias;
    float4 sf = self4[lane];
    float4 bf = bias4[lane];

#pragma unroll
    for (int it = 0; it < 7; it++) {
        int n = it * 8 + w;
        if (n < MAXK) {
            int rel = s_conn[2 * n], ent = s_conn[2 * n + 1];
            float4 a = ((const float4*)(g_P + (size_t)rel * 256))[lane];
            float4 bb = ((const float4*)(g_P + (size_t)ent * 256 + 128))[lane];
            float va[4] = {a.x + bb.x + bf.x, a.y + bb.y + bf.y,
                           a.z + bb.z + bf.z, a.w + bb.w + bf.w};
            float sfv[4] = {sf.x, sf.y, sf.z, sf.w};
            float dp = 0.f, nn = 0.f;
            float4 pv;
#pragma unroll
            for (int i = 0; i < 4; i++) {
                float v = va[i];
                v = (v > 0.f) ? v : 0.01f * v;
                if (rel == PADID) v = 0.f;
                (&pv.x)[i] = v;
                dp += sfv[i] * v;
                nn += v * v;
            }
            ((float4*)s_proj[n])[lane] = pv;
            for (int o = 16; o > 0; o >>= 1) {
                dp += __shfl_xor_sync(~0u, dp, o);
                nn += __shfl_xor_sync(~0u, nn, o);
            }
            if (lane == 0) {
                float nnei = sqrtf(nn + EPS);
                s_cos[n] = dp / (nself * nnei + EPS);
            }
        }
    }
    __syncthreads();

    if (w == 0) {
        float v0 = s_cos[lane];
        float v1 = (lane + 32 < MAXK) ? s_cos[lane + 32] : -3.0e38f;
#pragma unroll
        for (int k = 0; k < KNEI; k++) {
            float bv = v0; int bi = lane;
            if (v1 > bv) { bv = v1; bi = lane + 32; }
            for (int o = 16; o > 0; o >>= 1) {
                float ov = __shfl_xor_sync(~0u, bv, o);
                int   oi = __shfl_xor_sync(~0u, bi, o);
                if (ov > bv || (ov == bv && oi < bi)) { bv = ov; bi = oi; }
            }
            if (lane == 0) s_sel[k] = bi;
            if (bi == lane) v0 = -3.0e38f;
            else if (bi == lane + 32) v1 = -3.0e38f;
        }
    } else if (w == 1) {
        float gv = s_gw[lane];
        gv += (lane + 32 < MAXK) ? s_gw[lane + 32] : 0.f;
        for (int o = 16; o > 0; o >>= 1) gv += __shfl_xor_sync(~0u, gv, o);
        if (lane == 0) {
            float gate = fast_sig((gv / 50.f) / gate_temp[0]);
            if (deg <= 0) gate = 1.f;
            s_scal[1] = gate;
        }
    }
    __syncthreads();

    if (t < 128) {
        float agg = 0.f;
#pragma unroll
        for (int k = 0; k < KNEI; k++) agg += s_proj[s_sel[k]][t];
        agg /= 10.f;
        outp[t] = fast_tanh(s_self[t] + s_scal[1] * agg);
    }
}

// ---------------------------------------------------------------------------
// Support encoder stages
// ---------------------------------------------------------------------------
__global__ void se1_kernel(const float* __restrict__ W1, const float* __restrict__ b1)
{
    int gw = (blockIdx.x * blockDim.x + threadIdx.x) >> 5;
    int lane = threadIdx.x & 31;
    if (gw >= FEW * 512) return;
    int r = gw >> 9, j = gw & 511;
    const float4* x = (const float4*)(g_svec + r * 256);
    const float4* w = (const float4*)(W1 + (size_t)j * 256);
    float acc = 0.f;
#pragma unroll
    for (int k = lane; k < 64; k += 32) {
        float4 xv = x[k], wv = w[k];
        acc = fmaf(xv.x, wv.x, acc); acc = fmaf(xv.y, wv.y, acc);
        acc = fmaf(xv.z, wv.z, acc); acc = fmaf(xv.w, wv.w, acc);
    }
    for (int o = 16; o > 0; o >>= 1) acc += __shfl_xor_sync(~0u, acc, o);
    if (lane == 0) g_sh1[r * 512 + j] = fmaxf(acc + b1[j], 0.f);
}

__global__ void se2_kernel(const float* __restrict__ W2, const float* __restrict__ b2)
{
    int gw = (blockIdx.x * blockDim.x + threadIdx.x) >> 5;
    int lane = threadIdx.x & 31;
    if (gw >= FEW * 256) return;
    int r = gw >> 8, c = gw & 255;
    const float4* x = (const float4*)(g_sh1 + r * 512);
    const float4* w = (const float4*)(W2 + (size_t)c * 512);
    float acc = 0.f;
#pragma unroll
    for (int k = lane; k < 128; k += 32) {
        float4 xv = x[k], wv = w[k];
        acc = fmaf(xv.x, wv.x, acc); acc = fmaf(xv.y, wv.y, acc);
        acc = fmaf(xv.z, wv.z, acc); acc = fmaf(xv.w, wv.w, acc);
    }
    for (int o = 16; o > 0; o >>= 1) acc += __shfl_xor_sync(~0u, acc, o);
    if (lane == 0) g_sh[r * 256 + c] = acc + b2[c] + g_svec[r * 256 + c];
}

__global__ void se3_kernel(const float* __restrict__ g, const float* __restrict__ b)
{
    __shared__ float smu[FEW], srs[FEW];
    __shared__ float red[8];
    int t = threadIdx.x, lane = t & 31, w = t >> 5;

    if (w < FEW) {
        const float* row = g_sh + w * 256;
        float s = 0.f;
#pragma unroll
        for (int i = 0; i < 8; i++) s += row[lane + 32 * i];
        for (int o = 16; o > 0; o >>= 1) s += __shfl_xor_sync(~0u, s, o);
        float mu = s / 256.f;
        float q = 0.f;
#pragma unroll
        for (int i = 0; i < 8; i++) { float d = row[lane + 32 * i] - mu; q += d * d; }
        for (int o = 16; o > 0; o >>= 1) q += __shfl_xor_sync(~0u, q, o);
        if (lane == 0) { smu[w] = mu; srs[w] = 1.f / sqrtf(q / 256.f + LNEPS); }
    }
    __syncthreads();

    float acc = 0.f;
#pragma unroll
    for (int r = 0; r < FEW; r++)
        acc += g[t] * (g_sh[r * 256 + t] - smu[r]) * srs[r] + b[t];
    acc *= 0.2f;
    g_sg[t] = acc;

    float nq = acc * acc;
    for (int o = 16; o > 0; o >>= 1) nq += __shfl_xor_sync(~0u, nq, o);
    if (lane == 0) red[w] = nq;
    __syncthreads();
    if (t == 0) {
        float s = 0.f;
        for (int i = 0; i < 8; i++) s += red[i];
        g_sgn[0] = sqrtf(s + EPS);
    }
}

// ---------------------------------------------------------------------------
// LayerNorm rows of g_tmp -> g_X
// ---------------------------------------------------------------------------
__global__ void ln_kernel(const float* __restrict__ g, const float* __restrict__ b)
{
    int row = blockIdx.x, t = threadIdx.x;
    float v = g_tmp[(size_t)row * 256 + t];
    __shared__ float red[8];
    __shared__ float s_mu, s_rs;
    float s = v;
    for (int o = 16; o > 0; o >>= 1) s += __shfl_xor_sync(~0u, s, o);
    if ((t & 31) == 0) red[t >> 5] = s;
    __syncthreads();
    if (t == 0) { float m = 0.f; for (int i = 0; i < 8; i++) m += red[i]; s_mu = m / 256.f; }
    __syncthreads();
    float d = v - s_mu;
    float q = d * d;
    for (int o = 16; o > 0; o >>= 1) q += __shfl_xor_sync(~0u, q, o);
    if ((t & 31) == 0) red[t >> 5] = q;
    __syncthreads();
    if (t == 0) { float m = 0.f; for (int i = 0; i < 8; i++) m += red[i]; s_rs = 1.f / sqrtf(m / 256.f + LNEPS); }
    __syncthreads();
    g_X[(size_t)row * 256 + t] = g[t] * d * s_rs + b[t];
}

// ---------------------------------------------------------------------------
// Final cosine vs support_g
// ---------------------------------------------------------------------------
__global__ void final_kernel(const float* __restrict__ h_in, float* __restrict__ out)
{
    __shared__ float ssg[256];
    int t = threadIdx.x, lane = t & 31, w = t >> 5;
    ssg[t] = g_sg[t];
    __syncthreads();
    int row = blockIdx.x * 8 + w;
    const float* h = h_in + (size_t)row * 256;
    float dp = 0.f, nq = 0.f;
#pragma unroll
    for (int i = 0; i < 8; i++) {
        int d = lane + 32 * i;
        float v = h[d];
        dp += v * ssg[d];
        nq += v * v;
    }
    for (int o = 16; o > 0; o >>= 1) {
        dp += __shfl_xor_sync(~0u, dp, o);
        nq += __shfl_xor_sync(~0u, nq, o);
    }
    if (lane == 0) out[row] = dp / (sqrtf(nq + EPS) * g_sgn[0]);
}

// ---------------------------------------------------------------------------
// kernel_launch (single stream)
// ---------------------------------------------------------------------------
extern "C" void kernel_launch(void* const* d_in, const int* in_sizes, int n_in,
                              void* d_out, int out_size)
{
    const int*   query     = (const int*)d_in[0];
    const int*   support   = (const int*)d_in[1];
    const int*   q_l1      = (const int*)d_in[2];
    const int*   q_deg_l   = (const int*)d_in[3];
    const int*   q_r1      = (const int*)d_in[4];
    const int*   q_deg_r   = (const int*)d_in[5];
    const int*   s_l1      = (const int*)d_in[6];
    const int*   s_deg_l   = (const int*)d_in[7];
    const int*   s_r1      = (const int*)d_in[8];
    const int*   s_deg_r   = (const int*)d_in[9];
    const float* sym       = (const float*)d_in[10];
    const float* gcn_w_W   = (const float*)d_in[11];
    const float* gcn_w_b   = (const float*)d_in[12];
    const float* gcn_b     = (const float*)d_in[13];
    const float* gate_w    = (const float*)d_in[14];
    const float* gate_temp = (const float*)d_in[15];
    const float* se_W1     = (const float*)d_in[16];
    const float* se_b1     = (const float*)d_in[17];
    const float* se_W2     = (const float*)d_in[18];
    const float* se_b2     = (const float*)d_in[19];
    const float* ln_g      = (const float*)d_in[20];
    const float* ln_b      = (const float*)d_in[21];
    const float* lstm_Wih  = (const float*)d_in[22];
    const float* lstm_Whh  = (const float*)d_in[23];
    const float* lstm_bih  = (const float*)d_in[24];
    const float* lstm_bhh  = (const float*)d_in[25];
    float* out = (float*)d_out;

    float *pP, *pQv, *pH1, *pTmp, *pX, *pWihp, *pWhhLp, *pBsum, *pWhhr, *pH, *pH2, *pWt;
    __half* pGq;
    cudaGetSymbolAddress((void**)&pP,     g_P);
    cudaGetSymbolAddress((void**)&pWt,    g_Wt);
    cudaGetSymbolAddress((void**)&pQv,    g_qvec);
    cudaGetSymbolAddress((void**)&pH1,    g_H1);
    cudaGetSymbolAddress((void**)&pTmp,   g_tmp);
    cudaGetSymbolAddress((void**)&pX,     g_X);
    cudaGetSymbolAddress((void**)&pWihp,  g_Wihp);
    cudaGetSymbolAddress((void**)&pWhhLp, g_WhhLp);
    cudaGetSymbolAddress((void**)&pBsum,  g_bsum);
    cudaGetSymbolAddress((void**)&pWhhr,  g_whhr);
    cudaGetSymbolAddress((void**)&pGq,    g_Gq);
    cudaGetSymbolAddress((void**)&pH,     g_h);
    cudaGetSymbolAddress((void**)&pH2,    g_h2);

    const int SM_T = 2 * TBUFS * (int)sizeof(float);         // 73728
    const int SM_B = 4 * 128 * BSMS * (int)sizeof(uint32_t); // 40960
    static int attr_done = 0;
    if (!attr_done) {
        cudaFuncSetAttribute(tgemm_kernel<0>, cudaFuncAttributeMaxDynamicSharedMemorySize, SM_T);
        cudaFuncSetAttribute(tgemm_kernel<1>, cudaFuncAttributeMaxDynamicSharedMemorySize, SM_T);
        cudaFuncSetAttribute(tgemm_kernel<2>, cudaFuncAttributeMaxDynamicSharedMemorySize, SM_T);
        cudaFuncSetAttribute(bgemm_kernel,    cudaFuncAttributeMaxDynamicSharedMemorySize, SM_B);
        attr_done = 1;
    }

    // 1) merged weight packing
    pack_all_kernel<<<2176, 256>>>(gcn_w_W, lstm_Wih, lstm_bih, lstm_bhh, lstm_Whh);

    // 2) P = sym_emb @ Wt^T  (bf16x3)
    bgemm_kernel<<<dim3(2, (NSYM + 1 + 127) / 128), 256, SM_B>>>(
        sym, 128, pWt, 128, pP, 256, NSYM + 1, 256, 128);

    // 3) neighbor encoder -> g_qvec, g_svec
    neighbor_kernel<<<8202, 256>>>(query, support, q_l1, q_deg_l, q_r1, q_deg_r,
                                   s_l1, s_deg_l, s_r1, s_deg_r,
                                   sym, gcn_w_b, gcn_b, gate_w, gate_temp);

    // 4) query SE GEMM 1   <- ncu window
    tgemm_kernel<0><<<dim3(4, 32), 256, SM_T>>>(pQv, 256, se_W1, 256, pH1, 512,
                                                B, 512, 256, se_b1, nullptr, 0, 1, nullptr, nullptr);

    // 5-8) support encoder + whhr
    se1_kernel<<<(FEW * 512 + 7) / 8, 256>>>(se_W1, se_b1);
    se2_kernel<<<(FEW * 256 + 7) / 8, 256>>>(se_W2, se_b2);
    se3_kernel<<<1, 256>>>(ln_g, ln_b);
    prep_whhr_kernel<<<1024, 256>>>(lstm_Whh);

    // 9-10) query SE GEMM 2 + LN
    tgemm_kernel<0><<<dim3(2, 32), 256, SM_T>>>(pH1, 512, se_W2, 512, pTmp, 256,
                                                B, 256, 512, se_b2, pQv, 256, 0, nullptr, nullptr);
    ln_kernel<<<B, 256>>>(ln_g, ln_b);

    // 11) Gq = X @ Wihp^T + bsum (fp16 store); fused LSTM step 1 -> h in g_h
    tgemm_kernel<1><<<dim3(8, 32), 256, SM_T>>>(pX, 256, pWihp, 256, nullptr, 0,
                                                B, 1024, 256, pBsum, nullptr, 0, 0, pH, pGq);

    // 12-14) LSTM steps 2..4 (fused elementwise, fp16 Gq residual, double-buffered h)
    tgemm_kernel<2><<<dim3(8, 32), 256, SM_T>>>(pH, 256, pWhhLp, 256, nullptr, 0,
                                                B, 1024, 256, pWhhr, nullptr, 0, 0, pH2, pGq);
    tgemm_kernel<2><<<dim3(8, 32), 256, SM_T>>>(pH2, 256, pWhhLp, 256, nullptr, 0,
                                                B, 1024, 256, pWhhr, nullptr, 0, 0, pH, pGq);
    tgemm_kernel<2><<<dim3(8, 32), 256, SM_T>>>(pH, 256, pWhhLp, 256, nullptr, 0,
                                                B, 1024, 256, pWhhr, nullptr, 0, 0, pH2, pGq);

    // 15) final cosine
    final_kernel<<<B / 8, 256>>>(pH2, out);
}